// round 4
// baseline (speedup 1.0000x reference)
#include <cuda_runtime.h>

// Problem constants
#define MB 16
#define NT 512
#define DM 512
#define NH 8
#define DKH 64
#define MROWS (MB*NT)   // 8192

// ---------------- scratch (static device arrays; no cudaMalloc allowed) ----
static __device__ float g_h  [MROWS*DM];
static __device__ float g_q  [MROWS*DM];
static __device__ float g_k  [MROWS*DM];
static __device__ float g_v  [MROWS*DM];
static __device__ float g_ctx[MROWS*DM];
static __device__ float g_h2 [MROWS*DM];

// ---------------- packed f32x2 helpers (FFMA2 on sm_103a) ------------------
__device__ __forceinline__ unsigned long long pk2(float lo, float hi){
  unsigned long long r;
  asm("mov.b64 %0, {%1, %2};" : "=l"(r) : "f"(lo), "f"(hi));
  return r;
}
__device__ __forceinline__ void upk2(unsigned long long p, float& lo, float& hi){
  asm("mov.b64 {%0, %1}, %2;" : "=f"(lo), "=f"(hi) : "l"(p));
}
__device__ __forceinline__ unsigned long long ffma2(unsigned long long a,
                                                    unsigned long long b,
                                                    unsigned long long c){
  unsigned long long d;
  asm("fma.rn.f32x2 %0, %1, %2, %3;" : "=l"(d) : "l"(a), "l"(b), "l"(c));
  return d;
}
__device__ __forceinline__ unsigned long long fmul2(unsigned long long a,
                                                    unsigned long long b){
  unsigned long long d;
  asm("mul.rn.f32x2 %0, %1, %2;" : "=l"(d) : "l"(a), "l"(b));
  return d;
}

// ---------------- GEMM: C[8192,512] = A[8192,512] @ W[512,512] + bias ------
// 128x128 block tile, BK=16, 256 threads, 8x8 per thread via FFMA2.
#define ASTR 132
#define WSTR 132

__global__ __launch_bounds__(256,2) void gemm512(const float* __restrict__ A,
    const float* __restrict__ W, const float* __restrict__ bias,
    float* __restrict__ C, int relu)
{
  __shared__ float As[16*ASTR];  // [k][m] transposed
  __shared__ float Ws[16*WSTR];  // [k][n]
  const int tid = threadIdx.x;
  const int tx = tid & 15, ty = tid >> 4;
  const int m0 = blockIdx.y * 128;
  const int n0 = blockIdx.x * 128;

  unsigned long long acc[8][4];
#pragma unroll
  for (int i=0;i<8;i++)
#pragma unroll
    for (int j=0;j<4;j++) acc[i][j]=0ull;

  for (int k0=0;k0<512;k0+=16){
    __syncthreads();
    // A tile: 128 rows x 16 cols, store transposed
#pragma unroll
    for (int it=0; it<2; it++){
      int t4 = tid + it*256;
      int row = t4 >> 2;
      int c4  = t4 & 3;
      float4 v = *reinterpret_cast<const float4*>(&A[(size_t)(m0+row)*512 + k0 + c4*4]);
      As[(c4*4+0)*ASTR + row] = v.x;
      As[(c4*4+1)*ASTR + row] = v.y;
      As[(c4*4+2)*ASTR + row] = v.z;
      As[(c4*4+3)*ASTR + row] = v.w;
    }
    // W tile: 16 rows x 128 cols
#pragma unroll
    for (int it=0; it<2; it++){
      int t4 = tid + it*256;
      int rk = t4 >> 5;
      int c4 = t4 & 31;
      float4 v = *reinterpret_cast<const float4*>(&W[(size_t)(k0+rk)*512 + n0 + c4*4]);
      *reinterpret_cast<float4*>(&Ws[rk*WSTR + c4*4]) = v;
    }
    __syncthreads();
#pragma unroll
    for (int k=0;k<16;k++){
      float4 a0 = *reinterpret_cast<const float4*>(&As[k*ASTR + ty*8]);
      float4 a1 = *reinterpret_cast<const float4*>(&As[k*ASTR + ty*8 + 4]);
      float a[8] = {a0.x,a0.y,a0.z,a0.w,a1.x,a1.y,a1.z,a1.w};
      unsigned long long b[4];
#pragma unroll
      for (int j=0;j<4;j++)  // cols 2*tx + 32*j : conflict-free LDS.64
        b[j] = *reinterpret_cast<const unsigned long long*>(&Ws[k*WSTR + 2*tx + 32*j]);
#pragma unroll
      for (int i=0;i<8;i++){
        unsigned long long ap = pk2(a[i],a[i]);
#pragma unroll
        for (int j=0;j<4;j++)
          acc[i][j] = ffma2(ap, b[j], acc[i][j]);
      }
    }
  }
#pragma unroll
  for (int i=0;i<8;i++){
    int row = m0 + ty*8 + i;
#pragma unroll
    for (int j=0;j<4;j++){
      int col = n0 + 2*tx + 32*j;
      float lo,hi; upk2(acc[i][j],lo,hi);
      float c0 = lo + bias[col];
      float c1 = hi + bias[col+1];
      if (relu){ c0 = fmaxf(c0,0.f); c1 = fmaxf(c1,0.f); }
      *reinterpret_cast<float2*>(&C[(size_t)row*512 + col]) = make_float2(c0,c1);
    }
  }
}

// ---------------- LayerNorm (in place, one block per row) ------------------
__global__ void ln_kernel(float* __restrict__ h, const float* __restrict__ g,
                          const float* __restrict__ b)
{
  const int row = blockIdx.x;
  const int tid = threadIdx.x;
  float* hr = h + (size_t)row*512;
  float v0 = hr[tid], v1 = hr[tid+256];
  __shared__ float red[8], red2[8];
  float s = v0+v1;
#pragma unroll
  for (int o=16;o;o>>=1) s += __shfl_xor_sync(0xffffffffu,s,o);
  if ((tid&31)==0) red[tid>>5]=s;
  __syncthreads();
  float mu = (red[0]+red[1]+red[2]+red[3]+red[4]+red[5]+red[6]+red[7]) * (1.f/512.f);
  float d0 = v0-mu, d1 = v1-mu;
  float q = d0*d0 + d1*d1;
#pragma unroll
  for (int o=16;o;o>>=1) q += __shfl_xor_sync(0xffffffffu,q,o);
  if ((tid&31)==0) red2[tid>>5]=q;
  __syncthreads();
  float var = (red2[0]+red2[1]+red2[2]+red2[3]+red2[4]+red2[5]+red2[6]+red2[7]) * (1.f/512.f);
  float rstd = rsqrtf(var + 1e-5f);
  hr[tid]     = d0*rstd*g[tid]     + b[tid];
  hr[tid+256] = d1*rstd*g[tid+256] + b[tid+256];
}

// ---------------- Flash attention (fp32, online softmax) -------------------
// Block = (b, head, 64 q rows). 256 threads = 16x16.
// Masked scores become s*adj (exactly matches where(a>0,s,NEG)*a for a in {0,1}).
#define TSTR 66
#define ATTN_SMEM ((4*64*TSTR + 3*64)*4)

__global__ __launch_bounds__(256) void attn_kernel(
    const float* __restrict__ Q, const float* __restrict__ K,
    const float* __restrict__ V, const float* __restrict__ adj,
    const int* __restrict__ use_adj, float* __restrict__ ctx)
{
  extern __shared__ float sm[];
  float* Qs = sm;
  float* Ks = Qs + 64*TSTR;
  float* Vs = Ks + 64*TSTR;
  float* Ss = Vs + 64*TSTR;
  float* m_sm = Ss + 64*TSTR;
  float* l_sm = m_sm + 64;
  float* a_sm = l_sm + 64;

  const int tid = threadIdx.x;
  const int tx = tid & 15, ty = tid >> 4;
  const int q0 = blockIdx.x * 64;
  const int hh = blockIdx.y;
  const int bb = blockIdx.z;
  const int ua = use_adj[0];

  const float* qb = Q + ((size_t)bb*512)*512 + hh*64;
  const float* kp = K + ((size_t)bb*512)*512 + hh*64;
  const float* vp = V + ((size_t)bb*512)*512 + hh*64;
  const float* ab = adj + ((size_t)bb*512 + q0)*512;

  // Load Q tile (persistent)
#pragma unroll
  for (int it=0; it<4; it++){
    int t4 = tid + it*256;
    int row = t4 >> 4;
    int c4  = t4 & 15;
    float4 v = *reinterpret_cast<const float4*>(&qb[(size_t)(q0+row)*512 + c4*4]);
    *reinterpret_cast<float2*>(&Qs[row*TSTR + c4*4])   = make_float2(v.x,v.y);
    *reinterpret_cast<float2*>(&Qs[row*TSTR + c4*4+2]) = make_float2(v.z,v.w);
  }
  if (tid < 64){ m_sm[tid] = -1e30f; l_sm[tid] = 0.f; }

  unsigned long long o[4][2];
#pragma unroll
  for (int i=0;i<4;i++){o[i][0]=0ull;o[i][1]=0ull;}

  for (int kb0=0; kb0<512; kb0+=64){
    __syncthreads();  // covers init/Q-load on iter 0, prior-iter smem reads after
#pragma unroll
    for (int it=0; it<4; it++){
      int t4 = tid + it*256;
      int row = t4 >> 4;
      int c4  = t4 & 15;
      float4 kv = *reinterpret_cast<const float4*>(&kp[(size_t)(kb0+row)*512 + c4*4]);
      *reinterpret_cast<float2*>(&Ks[row*TSTR + c4*4])   = make_float2(kv.x,kv.y);
      *reinterpret_cast<float2*>(&Ks[row*TSTR + c4*4+2]) = make_float2(kv.z,kv.w);
      float4 vv = *reinterpret_cast<const float4*>(&vp[(size_t)(kb0+row)*512 + c4*4]);
      *reinterpret_cast<float2*>(&Vs[row*TSTR + c4*4])   = make_float2(vv.x,vv.y);
      *reinterpret_cast<float2*>(&Vs[row*TSTR + c4*4+2]) = make_float2(vv.z,vv.w);
    }
    __syncthreads();

    // S = Q K^T (packed along d, 4x4 per thread, cols tx+16j)
    unsigned long long sacc[4][4];
#pragma unroll
    for (int i=0;i<4;i++)
#pragma unroll
      for (int j=0;j<4;j++) sacc[i][j]=0ull;

#pragma unroll 8
    for (int dp=0; dp<32; dp++){
      unsigned long long aq[4], bkp[4];
#pragma unroll
      for (int i=0;i<4;i++)
        aq[i] = *reinterpret_cast<const unsigned long long*>(&Qs[(ty*4+i)*TSTR + dp*2]);
#pragma unroll
      for (int j=0;j<4;j++)
        bkp[j] = *reinterpret_cast<const unsigned long long*>(&Ks[(tx+16*j)*TSTR + dp*2]);
#pragma unroll
      for (int i=0;i<4;i++)
#pragma unroll
        for (int j=0;j<4;j++)
          sacc[i][j] = ffma2(aq[i], bkp[j], sacc[i][j]);
    }

#pragma unroll
    for (int i=0;i<4;i++){
      int r = ty*4+i;
#pragma unroll
      for (int j=0;j<4;j++){
        float lo,hi; upk2(sacc[i][j],lo,hi);
        float sv = (lo+hi)*0.125f;
        if (ua) sv *= ab[(size_t)r*512 + kb0 + tx + 16*j];
        Ss[r*TSTR + tx + 16*j] = sv;
      }
    }
    __syncthreads();

    // Online softmax: 8 warps x 8 rows
    {
      const int w = tid>>5, lane = tid&31;
#pragma unroll
      for (int rr=0; rr<8; rr++){
        int r = w*8+rr;
        float s0 = Ss[r*TSTR + lane];
        float s1 = Ss[r*TSTR + 32 + lane];
        float mx = fmaxf(s0,s1);
#pragma unroll
        for (int off=16;off;off>>=1) mx = fmaxf(mx, __shfl_xor_sync(0xffffffffu,mx,off));
        float mo = m_sm[r];
        float mn = fmaxf(mo,mx);
        float p0 = __expf(s0-mn), p1 = __expf(s1-mn);
        Ss[r*TSTR+lane]=p0; Ss[r*TSTR+32+lane]=p1;
        float sum = p0+p1;
#pragma unroll
        for (int off=16;off;off>>=1) sum += __shfl_xor_sync(0xffffffffu,sum,off);
        if (lane==0){
          float alpha = __expf(mo-mn);     // 0 on first iteration (mo=-1e30)
          l_sm[r] = l_sm[r]*alpha + sum;
          m_sm[r] = mn;
          a_sm[r] = alpha;
        }
      }
    }
    __syncthreads();

    // O = O*alpha + P @ V (dims 2tx+32jp, packed pairs)
#pragma unroll
    for (int i=0;i<4;i++){
      float al = a_sm[ty*4+i];
      unsigned long long ap = pk2(al,al);
      o[i][0] = fmul2(ap,o[i][0]);
      o[i][1] = fmul2(ap,o[i][1]);
    }
#pragma unroll 4
    for (int kk=0; kk<64; kk++){
      unsigned long long v0 = *reinterpret_cast<const unsigned long long*>(&Vs[kk*TSTR + 2*tx]);
      unsigned long long v1 = *reinterpret_cast<const unsigned long long*>(&Vs[kk*TSTR + 2*tx + 32]);
#pragma unroll
      for (int i=0;i<4;i++){
        float p = Ss[(ty*4+i)*TSTR + kk];
        unsigned long long pp = pk2(p,p);
        o[i][0] = ffma2(pp, v0, o[i][0]);
        o[i][1] = ffma2(pp, v1, o[i][1]);
      }
    }
  }

#pragma unroll
  for (int i=0;i<4;i++){
    int r = ty*4+i;
    float inv = 1.f/l_sm[r];
#pragma unroll
    for (int jp=0;jp<2;jp++){
      float lo,hi; upk2(o[i][jp],lo,hi);
      size_t base = ((size_t)bb*512 + q0 + r)*512 + hh*64 + 2*tx + 32*jp;
      ctx[base]   = lo*inv;
      ctx[base+1] = hi*inv;
    }
  }
}

// ---------------- Gate + blend: out = c*x + (1-c)*h2 -----------------------
__global__ void gate_kernel(const float* __restrict__ x, const float* __restrict__ h2,
    const float* __restrict__ gw, const float* __restrict__ gb, float* __restrict__ out)
{
  const int w = threadIdx.x>>5, lane = threadIdx.x&31;
  const int row = blockIdx.x*8 + w;
  const float* xr = x  + (size_t)row*512;
  const float* hr = h2 + (size_t)row*512;
  float s = 0.f;
#pragma unroll
  for (int i=0;i<16;i++){
    int c = i*32 + lane;
    s += xr[c]*gw[c] + hr[c]*gw[512+c];
  }
#pragma unroll
  for (int off=16;off;off>>=1) s += __shfl_xor_sync(0xffffffffu,s,off);
  s += gb[0];
  float coeff = 1.f/(1.f+__expf(-s));
  float* orow = out + (size_t)row*512;
#pragma unroll
  for (int i=0;i<16;i++){
    int c = i*32+lane;
    orow[c] = coeff*xr[c] + (1.f-coeff)*hr[c];
  }
}

// ---------------- launch ---------------------------------------------------
extern "C" void kernel_launch(void* const* d_in, const int* in_sizes, int n_in,
                              void* d_out, int out_size)
{
  const float* x   = (const float*)d_in[0];
  const float* adj = (const float*)d_in[1];
  const float* W_w = (const float*)d_in[2];
  const float* W_b = (const float*)d_in[3];
  const float* lng = (const float*)d_in[4];
  const float* lnb = (const float*)d_in[5];
  const float* Wq  = (const float*)d_in[6];
  const float* bq  = (const float*)d_in[7];
  const float* Wk  = (const float*)d_in[8];
  const float* bk  = (const float*)d_in[9];
  const float* Wv  = (const float*)d_in[10];
  const float* bv  = (const float*)d_in[11];
  const float* Wo  = (const float*)d_in[12];
  const float* bo  = (const float*)d_in[13];
  const float* gw  = (const float*)d_in[14];
  const float* gbb = (const float*)d_in[15];
  const int*   ua  = (const int*)d_in[16];
  float* out = (float*)d_out;

  float *h,*q,*k,*v,*ctx,*h2;
  cudaGetSymbolAddress((void**)&h,   g_h);
  cudaGetSymbolAddress((void**)&q,   g_q);
  cudaGetSymbolAddress((void**)&k,   g_k);
  cudaGetSymbolAddress((void**)&v,   g_v);
  cudaGetSymbolAddress((void**)&ctx, g_ctx);
  cudaGetSymbolAddress((void**)&h2,  g_h2);

  cudaFuncSetAttribute(attn_kernel, cudaFuncAttributeMaxDynamicSharedMemorySize, ATTN_SMEM);

  dim3 gg(4,64);  // (N/128, M/128)
  gemm512<<<gg,256>>>(x, W_w, W_b, h, 0);
  ln_kernel<<<8192,256>>>(h, lng, lnb);
  gemm512<<<gg,256>>>(h, Wq, bq, q, 0);
  gemm512<<<gg,256>>>(h, Wk, bk, k, 0);
  gemm512<<<gg,256>>>(h, Wv, bv, v, 0);
  attn_kernel<<<dim3(8,8,16),256,ATTN_SMEM>>>(q, k, v, adj, ua, ctx);
  gemm512<<<gg,256>>>(ctx, Wo, bo, h2, 1);
  gate_kernel<<<1024,256>>>(x, h2, gw, gbb, out);
}

// round 6
// speedup vs baseline: 1.1744x; 1.1744x over previous
#include <cuda_runtime.h>
#include <cuda_bf16.h>
#include <cstdint>

// Problem constants
#define MB 16
#define NT 512
#define DM 512
#define MROWS (MB*NT)   // 8192

// ---------------- scratch (static device arrays; no cudaMalloc allowed) ----
static __device__ float g_h  [MROWS*DM];
static __device__ float g_q  [MROWS*DM];
static __device__ float g_k  [MROWS*DM];
static __device__ float g_v  [MROWS*DM];
static __device__ float g_ctx[MROWS*DM];
static __device__ float g_h2 [MROWS*DM];

// bf16 hi/lo splits of activations
static __device__ __nv_bfloat16 g_xh[MROWS*DM], g_xl[MROWS*DM];
static __device__ __nv_bfloat16 g_hh[MROWS*DM], g_hl[MROWS*DM];
static __device__ __nv_bfloat16 g_ch[MROWS*DM], g_cl[MROWS*DM];
// bf16 hi/lo of transposed weights (stored [n,k] so D = A·B^T = A·W)
static __device__ __nv_bfloat16 g_wwh[DM*DM], g_wwl[DM*DM];
static __device__ __nv_bfloat16 g_wqh[DM*DM], g_wql[DM*DM];
static __device__ __nv_bfloat16 g_wkh[DM*DM], g_wkl[DM*DM];
static __device__ __nv_bfloat16 g_wvh[DM*DM], g_wvl[DM*DM];
static __device__ __nv_bfloat16 g_woh[DM*DM], g_wol[DM*DM];

// ---------------- packed f32x2 helpers (FFMA2, used by attention) ----------
__device__ __forceinline__ unsigned long long pk2(float lo, float hi){
  unsigned long long r;
  asm("mov.b64 %0, {%1, %2};" : "=l"(r) : "f"(lo), "f"(hi));
  return r;
}
__device__ __forceinline__ void upk2(unsigned long long p, float& lo, float& hi){
  asm("mov.b64 {%0, %1}, %2;" : "=f"(lo), "=f"(hi) : "l"(p));
}
__device__ __forceinline__ unsigned long long ffma2(unsigned long long a,
                                                    unsigned long long b,
                                                    unsigned long long c){
  unsigned long long d;
  asm("fma.rn.f32x2 %0, %1, %2, %3;" : "=l"(d) : "l"(a), "l"(b), "l"(c));
  return d;
}
__device__ __forceinline__ unsigned long long fmul2(unsigned long long a,
                                                    unsigned long long b){
  unsigned long long d;
  asm("mul.rn.f32x2 %0, %1, %2;" : "=l"(d) : "l"(a), "l"(b));
  return d;
}

__device__ __forceinline__ uint32_t s2u(const void* p){
  return (uint32_t)__cvta_generic_to_shared(p);
}

// ---------------- mma.sync helpers -----------------------------------------
__device__ __forceinline__ void ldsm4(uint32_t* r, uint32_t addr){
  asm volatile("ldmatrix.sync.aligned.m8n8.x4.shared.b16 {%0,%1,%2,%3}, [%4];"
   : "=r"(r[0]),"=r"(r[1]),"=r"(r[2]),"=r"(r[3]) : "r"(addr));
}
__device__ __forceinline__ void mma16816(float* d, const uint32_t* a, const uint32_t* b){
  asm volatile("mma.sync.aligned.m16n8k16.row.col.f32.bf16.bf16.f32 "
    "{%0,%1,%2,%3}, {%4,%5,%6,%7}, {%8,%9}, {%0,%1,%2,%3};"
    : "+f"(d[0]),"+f"(d[1]),"+f"(d[2]),"+f"(d[3])
    : "r"(a[0]),"r"(a[1]),"r"(a[2]),"r"(a[3]), "r"(b[0]),"r"(b[1]));
}

// ---------------- mma.sync GEMM: C[8192,512] = A @ W + bias ----------------
// A bf16 hi/lo [8192,512]; W transposed bf16 hi/lo [512(n),512(k)].
// 3 split terms (AhBh, AhBl, AlBh) accumulated in fp32 registers.
// CTA tile 128x128, BK=64, 8 warps (4x2), warp tile 32x64, cp.async 2-stage.
#define SA 72                        // smem row stride in halves (144B)
#define ABYTES (128*SA*2)            // 18432 per tile
#define STGB   (2*ABYTES)            // A + W per stage = 36864
#define GEMM_SMEM (2*STGB)           // 73728

__global__ __launch_bounds__(256,2) void gemm_mma(
    const __nv_bfloat16* __restrict__ Ah, const __nv_bfloat16* __restrict__ Al,
    const __nv_bfloat16* __restrict__ Bh, const __nv_bfloat16* __restrict__ Bl,
    const float* __restrict__ bias, float* __restrict__ C, int relu)
{
  extern __shared__ __align__(16) char smem_raw[];
  const int tid  = threadIdx.x;
  const int lane = tid & 31, wid = tid >> 5;
  const int warpM = wid >> 1, warpN = wid & 1;
  const int m0 = blockIdx.y * 128;
  const int n0 = blockIdx.x * 128;

  float acc[2][8][4];
#pragma unroll
  for (int i=0;i<2;i++)
#pragma unroll
    for (int j=0;j<8;j++)
#pragma unroll
      for (int r=0;r<4;r++) acc[i][j][r]=0.f;

  const uint32_t sbase = s2u(smem_raw);
  const int ldRow = tid >> 1;
  const int ldSeg = (tid & 1) * 32;

  // ldmatrix lane addressing (byte offsets within a stage)
  const uint32_t a_lane_off = (uint32_t)(((warpM*32 + (lane & 15)) * SA + (lane >> 4) * 8) * 2);
  const int n_off = ((lane >> 4) & 1) * 8 + (lane & 7);
  const int k_off = ((lane >> 3) & 1) * 8;
  uint32_t b_lane_off[4];
#pragma unroll
  for (int nip=0; nip<4; nip++)
    b_lane_off[nip] = (uint32_t)(((warpN*64 + nip*16 + n_off) * SA + k_off) * 2);

#define NC 24
  // chunk c: term = c/8 (0: AhBh, 1: AhBl, 2: AlBh), k0 = (c%8)*64
#define LOAD_CHUNK(s, c) do { \
    const __nv_bfloat16* Asrc = ((c) >= 16) ? Al : Ah; \
    const __nv_bfloat16* Wsrc = ((c) >= 8 && (c) < 16) ? Bl : Bh; \
    const int kk0 = ((c) & 7) * 64; \
    uint32_t da = sbase + (s)*STGB + (uint32_t)((ldRow*SA + ldSeg)*2); \
    uint32_t dw = da + ABYTES; \
    const __nv_bfloat16* ga = Asrc + (size_t)(m0 + ldRow)*512 + kk0 + ldSeg; \
    const __nv_bfloat16* gw = Wsrc + (size_t)(n0 + ldRow)*512 + kk0 + ldSeg; \
    _Pragma("unroll") \
    for (int j=0;j<4;j++){ \
      asm volatile("cp.async.cg.shared.global [%0], [%1], 16;" :: "r"(da + j*16), "l"(ga + j*8)); \
      asm volatile("cp.async.cg.shared.global [%0], [%1], 16;" :: "r"(dw + j*16), "l"(gw + j*8)); \
    } \
  } while(0)

  LOAD_CHUNK(0, 0);
  asm volatile("cp.async.commit_group;" ::: "memory");

  for (int c=0; c<NC; c++){
    const int s = c & 1;
    if (c+1 < NC){
      LOAD_CHUNK(s^1, c+1);
      asm volatile("cp.async.commit_group;" ::: "memory");
      asm volatile("cp.async.wait_group 1;" ::: "memory");
    } else {
      asm volatile("cp.async.wait_group 0;" ::: "memory");
    }
    __syncthreads();

    const uint32_t abase = sbase + s*STGB + a_lane_off;
    const uint32_t bbase = sbase + s*STGB + ABYTES;
#pragma unroll
    for (int k16=0; k16<4; k16++){
      uint32_t af[2][4];
      ldsm4(af[0], abase + k16*32);
      ldsm4(af[1], abase + 16*SA*2 + k16*32);
#pragma unroll
      for (int nip=0; nip<4; nip++){
        uint32_t bf[4];
        ldsm4(bf, bbase + b_lane_off[nip] + k16*32);
        mma16816(acc[0][2*nip],   af[0], bf);
        mma16816(acc[0][2*nip+1], af[0], bf+2);
        mma16816(acc[1][2*nip],   af[1], bf);
        mma16816(acc[1][2*nip+1], af[1], bf+2);
      }
    }
    __syncthreads();
  }

  // Epilogue
  const int g  = lane >> 2;
  const int tg = lane & 3;
#pragma unroll
  for (int mi=0; mi<2; mi++){
    const int row = m0 + warpM*32 + mi*16 + g;
#pragma unroll
    for (int ni=0; ni<8; ni++){
      const int col = n0 + warpN*64 + ni*8 + tg*2;
      const float b0 = bias[col], b1 = bias[col+1];
      float2 v0 = make_float2(acc[mi][ni][0]+b0, acc[mi][ni][1]+b1);
      float2 v1 = make_float2(acc[mi][ni][2]+b0, acc[mi][ni][3]+b1);
      if (relu){
        v0.x = fmaxf(v0.x,0.f); v0.y = fmaxf(v0.y,0.f);
        v1.x = fmaxf(v1.x,0.f); v1.y = fmaxf(v1.y,0.f);
      }
      *reinterpret_cast<float2*>(&C[(size_t)row*512 + col])     = v0;
      *reinterpret_cast<float2*>(&C[(size_t)(row+8)*512 + col]) = v1;
    }
  }
}

// ---------------- fp32 -> bf16 hi/lo split (vectorized) --------------------
__global__ void split_hl(const float* __restrict__ in,
                         __nv_bfloat16* __restrict__ hi,
                         __nv_bfloat16* __restrict__ lo)
{
  int i = blockIdx.x*256 + threadIdx.x;   // over quads
  float4 v = reinterpret_cast<const float4*>(in)[i];
  float f[4] = {v.x, v.y, v.z, v.w};
  __nv_bfloat16 h[4], l[4];
#pragma unroll
  for (int j=0;j<4;j++){
    h[j] = __float2bfloat16(f[j]);
    l[j] = __float2bfloat16(f[j] - __bfloat162float(h[j]));
  }
  reinterpret_cast<__nv_bfloat162*>(hi)[2*i]   = __halves2bfloat162(h[0], h[1]);
  reinterpret_cast<__nv_bfloat162*>(hi)[2*i+1] = __halves2bfloat162(h[2], h[3]);
  reinterpret_cast<__nv_bfloat162*>(lo)[2*i]   = __halves2bfloat162(l[0], l[1]);
  reinterpret_cast<__nv_bfloat162*>(lo)[2*i+1] = __halves2bfloat162(l[2], l[3]);
}

// ---------------- W[512,512] -> transposed bf16 hi/lo [n,k] ----------------
__global__ void tsplit(const float* __restrict__ W,
                       __nv_bfloat16* __restrict__ Th,
                       __nv_bfloat16* __restrict__ Tl)
{
  __shared__ float t[32][33];
  const int bx = blockIdx.x*32;  // n
  const int by = blockIdx.y*32;  // k
  const int txx = threadIdx.x, tyy = threadIdx.y;
#pragma unroll
  for (int i=tyy;i<32;i+=8)
    t[i][txx] = W[(size_t)(by+i)*512 + bx + txx];
  __syncthreads();
#pragma unroll
  for (int i=tyy;i<32;i+=8){
    float v = t[txx][i];            // = W[by+txx][bx+i]
    __nv_bfloat16 h = __float2bfloat16(v);
    __nv_bfloat16 l = __float2bfloat16(v - __bfloat162float(h));
    Th[(size_t)(bx+i)*512 + by + txx] = h;
    Tl[(size_t)(bx+i)*512 + by + txx] = l;
  }
}

// ---------------- LayerNorm + bf16 split (one block per row) ---------------
__global__ void ln_split(const float* __restrict__ h, const float* __restrict__ g,
                         const float* __restrict__ b,
                         __nv_bfloat16* __restrict__ hh, __nv_bfloat16* __restrict__ hl)
{
  const int row = blockIdx.x;
  const int tid = threadIdx.x;
  const float* hr = h + (size_t)row*512;
  float v0 = hr[tid], v1 = hr[tid+256];
  __shared__ float red[8], red2[8];
  float s = v0+v1;
#pragma unroll
  for (int o=16;o;o>>=1) s += __shfl_xor_sync(0xffffffffu,s,o);
  if ((tid&31)==0) red[tid>>5]=s;
  __syncthreads();
  float mu = (red[0]+red[1]+red[2]+red[3]+red[4]+red[5]+red[6]+red[7]) * (1.f/512.f);
  float d0 = v0-mu, d1 = v1-mu;
  float q = d0*d0 + d1*d1;
#pragma unroll
  for (int o=16;o;o>>=1) q += __shfl_xor_sync(0xffffffffu,q,o);
  if ((tid&31)==0) red2[tid>>5]=q;
  __syncthreads();
  float var = (red2[0]+red2[1]+red2[2]+red2[3]+red2[4]+red2[5]+red2[6]+red2[7]) * (1.f/512.f);
  float rstd = rsqrtf(var + 1e-5f);
  float o0 = d0*rstd*g[tid]     + b[tid];
  float o1 = d1*rstd*g[tid+256] + b[tid+256];
  __nv_bfloat16 h0 = __float2bfloat16(o0);
  __nv_bfloat16 h1 = __float2bfloat16(o1);
  hh[(size_t)row*512 + tid]     = h0;
  hh[(size_t)row*512 + tid+256] = h1;
  hl[(size_t)row*512 + tid]     = __float2bfloat16(o0 - __bfloat162float(h0));
  hl[(size_t)row*512 + tid+256] = __float2bfloat16(o1 - __bfloat162float(h1));
}

// ---------------- Flash attention (fp32, online softmax) -------------------
#define TSTR 66
#define ATTN_SMEM ((4*64*TSTR + 3*64)*4)

__global__ __launch_bounds__(256) void attn_kernel(
    const float* __restrict__ Q, const float* __restrict__ K,
    const float* __restrict__ V, const float* __restrict__ adj,
    const int* __restrict__ use_adj, float* __restrict__ ctx)
{
  extern __shared__ float sm[];
  float* Qs = sm;
  float* Ks = Qs + 64*TSTR;
  float* Vs = Ks + 64*TSTR;
  float* Ss = Vs + 64*TSTR;
  float* m_sm = Ss + 64*TSTR;
  float* l_sm = m_sm + 64;
  float* a_sm = l_sm + 64;

  const int tid = threadIdx.x;
  const int tx = tid & 15, ty = tid >> 4;
  const int q0 = blockIdx.x * 64;
  const int hh = blockIdx.y;
  const int bb = blockIdx.z;
  const int ua = use_adj[0];

  const float* qb = Q + ((size_t)bb*512)*512 + hh*64;
  const float* kp = K + ((size_t)bb*512)*512 + hh*64;
  const float* vp = V + ((size_t)bb*512)*512 + hh*64;
  const float* ab = adj + ((size_t)bb*512 + q0)*512;

#pragma unroll
  for (int it=0; it<4; it++){
    int t4 = tid + it*256;
    int row = t4 >> 4;
    int c4  = t4 & 15;
    float4 v = *reinterpret_cast<const float4*>(&qb[(size_t)(q0+row)*512 + c4*4]);
    *reinterpret_cast<float2*>(&Qs[row*TSTR + c4*4])   = make_float2(v.x,v.y);
    *reinterpret_cast<float2*>(&Qs[row*TSTR + c4*4+2]) = make_float2(v.z,v.w);
  }
  if (tid < 64){ m_sm[tid] = -1e30f; l_sm[tid] = 0.f; }

  unsigned long long o[4][2];
#pragma unroll
  for (int i=0;i<4;i++){o[i][0]=0ull;o[i][1]=0ull;}

  for (int kb0=0; kb0<512; kb0+=64){
    __syncthreads();
#pragma unroll
    for (int it=0; it<4; it++){
      int t4 = tid + it*256;
      int row = t4 >> 4;
      int c4  = t4 & 15;
      float4 kv = *reinterpret_cast<const float4*>(&kp[(size_t)(kb0+row)*512 + c4*4]);
      *reinterpret_cast<float2*>(&Ks[row*TSTR + c4*4])   = make_float2(kv.x,kv.y);
      *reinterpret_cast<float2*>(&Ks[row*TSTR + c4*4+2]) = make_float2(kv.z,kv.w);
      float4 vv = *reinterpret_cast<const float4*>(&vp[(size_t)(kb0+row)*512 + c4*4]);
      *reinterpret_cast<float2*>(&Vs[row*TSTR + c4*4])   = make_float2(vv.x,vv.y);
      *reinterpret_cast<float2*>(&Vs[row*TSTR + c4*4+2]) = make_float2(vv.z,vv.w);
    }
    __syncthreads();

    unsigned long long sacc[4][4];
#pragma unroll
    for (int i=0;i<4;i++)
#pragma unroll
      for (int j=0;j<4;j++) sacc[i][j]=0ull;

#pragma unroll 8
    for (int dp=0; dp<32; dp++){
      unsigned long long aq[4], bkp[4];
#pragma unroll
      for (int i=0;i<4;i++)
        aq[i] = *reinterpret_cast<const unsigned long long*>(&Qs[(ty*4+i)*TSTR + dp*2]);
#pragma unroll
      for (int j=0;j<4;j++)
        bkp[j] = *reinterpret_cast<const unsigned long long*>(&Ks[(tx+16*j)*TSTR + dp*2]);
#pragma unroll
      for (int i=0;i<4;i++)
#pragma unroll
        for (int j=0;j<4;j++)
          sacc[i][j] = ffma2(aq[i], bkp[j], sacc[i][j]);
    }

#pragma unroll
    for (int i=0;i<4;i++){
      int r = ty*4+i;
#pragma unroll
      for (int j=0;j<4;j++){
        float lo,hi; upk2(sacc[i][j],lo,hi);
        float sv = (lo+hi)*0.125f;
        if (ua) sv *= ab[(size_t)r*512 + kb0 + tx + 16*j];
        Ss[r*TSTR + tx + 16*j] = sv;
      }
    }
    __syncthreads();

    {
      const int w = tid>>5, lane = tid&31;
#pragma unroll
      for (int rr=0; rr<8; rr++){
        int r = w*8+rr;
        float s0 = Ss[r*TSTR + lane];
        float s1 = Ss[r*TSTR + 32 + lane];
        float mx = fmaxf(s0,s1);
#pragma unroll
        for (int off=16;off;off>>=1) mx = fmaxf(mx, __shfl_xor_sync(0xffffffffu,mx,off));
        float mo = m_sm[r];
        float mn = fmaxf(mo,mx);
        float p0 = __expf(s0-mn), p1 = __expf(s1-mn);
        Ss[r*TSTR+lane]=p0; Ss[r*TSTR+32+lane]=p1;
        float sum = p0+p1;
#pragma unroll
        for (int off=16;off;off>>=1) sum += __shfl_xor_sync(0xffffffffu,sum,off);
        if (lane==0){
          float alpha = __expf(mo-mn);
          l_sm[r] = l_sm[r]*alpha + sum;
          m_sm[r] = mn;
          a_sm[r] = alpha;
        }
      }
    }
    __syncthreads();

#pragma unroll
    for (int i=0;i<4;i++){
      float al = a_sm[ty*4+i];
      unsigned long long ap = pk2(al,al);
      o[i][0] = fmul2(ap,o[i][0]);
      o[i][1] = fmul2(ap,o[i][1]);
    }
#pragma unroll 4
    for (int kk=0; kk<64; kk++){
      unsigned long long v0 = *reinterpret_cast<const unsigned long long*>(&Vs[kk*TSTR + 2*tx]);
      unsigned long long v1 = *reinterpret_cast<const unsigned long long*>(&Vs[kk*TSTR + 2*tx + 32]);
#pragma unroll
      for (int i=0;i<4;i++){
        float p = Ss[(ty*4+i)*TSTR + kk];
        unsigned long long pp = pk2(p,p);
        o[i][0] = ffma2(pp, v0, o[i][0]);
        o[i][1] = ffma2(pp, v1, o[i][1]);
      }
    }
  }

#pragma unroll
  for (int i=0;i<4;i++){
    int r = ty*4+i;
    float inv = 1.f/l_sm[r];
#pragma unroll
    for (int jp=0;jp<2;jp++){
      float lo,hi; upk2(o[i][jp],lo,hi);
      size_t base = ((size_t)bb*512 + q0 + r)*512 + hh*64 + 2*tx + 32*jp;
      ctx[base]   = lo*inv;
      ctx[base+1] = hi*inv;
    }
  }
}

// ---------------- Gate + blend: out = c*x + (1-c)*h2 -----------------------
__global__ void gate_kernel(const float* __restrict__ x, const float* __restrict__ h2,
    const float* __restrict__ gw, const float* __restrict__ gb, float* __restrict__ out)
{
  const int w = threadIdx.x>>5, lane = threadIdx.x&31;
  const int row = blockIdx.x*8 + w;
  const float* xr = x  + (size_t)row*512;
  const float* hr = h2 + (size_t)row*512;
  float s = 0.f;
#pragma unroll
  for (int i=0;i<16;i++){
    int c = i*32 + lane;
    s += xr[c]*gw[c] + hr[c]*gw[512+c];
  }
#pragma unroll
  for (int off=16;off;off>>=1) s += __shfl_xor_sync(0xffffffffu,s,off);
  s += gb[0];
  float coeff = 1.f/(1.f+__expf(-s));
  float* orow = out + (size_t)row*512;
#pragma unroll
  for (int i=0;i<16;i++){
    int c = i*32+lane;
    orow[c] = coeff*xr[c] + (1.f-coeff)*hr[c];
  }
}

// ---------------- launch ---------------------------------------------------
extern "C" void kernel_launch(void* const* d_in, const int* in_sizes, int n_in,
                              void* d_out, int out_size)
{
  const float* x   = (const float*)d_in[0];
  const float* adj = (const float*)d_in[1];
  const float* W_w = (const float*)d_in[2];
  const float* W_b = (const float*)d_in[3];
  const float* lng = (const float*)d_in[4];
  const float* lnb = (const float*)d_in[5];
  const float* Wq  = (const float*)d_in[6];
  const float* bq  = (const float*)d_in[7];
  const float* Wk  = (const float*)d_in[8];
  const float* bk  = (const float*)d_in[9];
  const float* Wv  = (const float*)d_in[10];
  const float* bv  = (const float*)d_in[11];
  const float* Wo  = (const float*)d_in[12];
  const float* bo  = (const float*)d_in[13];
  const float* gw  = (const float*)d_in[14];
  const float* gbb = (const float*)d_in[15];
  const int*   ua  = (const int*)d_in[16];
  float* out = (float*)d_out;

  float *h,*q,*k,*v,*ctx,*h2;
  cudaGetSymbolAddress((void**)&h,   g_h);
  cudaGetSymbolAddress((void**)&q,   g_q);
  cudaGetSymbolAddress((void**)&k,   g_k);
  cudaGetSymbolAddress((void**)&v,   g_v);
  cudaGetSymbolAddress((void**)&ctx, g_ctx);
  cudaGetSymbolAddress((void**)&h2,  g_h2);

  __nv_bfloat16 *xh,*xl,*hh,*hl,*ch,*cl;
  __nv_bfloat16 *wwh,*wwl,*wqh,*wql,*wkh,*wkl,*wvh,*wvl,*woh,*wol;
  cudaGetSymbolAddress((void**)&xh, g_xh);  cudaGetSymbolAddress((void**)&xl, g_xl);
  cudaGetSymbolAddress((void**)&hh, g_hh);  cudaGetSymbolAddress((void**)&hl, g_hl);
  cudaGetSymbolAddress((void**)&ch, g_ch);  cudaGetSymbolAddress((void**)&cl, g_cl);
  cudaGetSymbolAddress((void**)&wwh, g_wwh); cudaGetSymbolAddress((void**)&wwl, g_wwl);
  cudaGetSymbolAddress((void**)&wqh, g_wqh); cudaGetSymbolAddress((void**)&wql, g_wql);
  cudaGetSymbolAddress((void**)&wkh, g_wkh); cudaGetSymbolAddress((void**)&wkl, g_wkl);
  cudaGetSymbolAddress((void**)&wvh, g_wvh); cudaGetSymbolAddress((void**)&wvl, g_wvl);
  cudaGetSymbolAddress((void**)&woh, g_woh); cudaGetSymbolAddress((void**)&wol, g_wol);

  cudaFuncSetAttribute(attn_kernel, cudaFuncAttributeMaxDynamicSharedMemorySize, ATTN_SMEM);
  cudaFuncSetAttribute(gemm_mma,    cudaFuncAttributeMaxDynamicSharedMemorySize, GEMM_SMEM);

  dim3 tsg(16,16), tsb(32,8);
  dim3 gg(4,64);   // n-tiles x m-tiles (128x128 each) = 256 CTAs

  // weight transposed hi/lo splits
  tsplit<<<tsg,tsb>>>(W_w, wwh, wwl);
  tsplit<<<tsg,tsb>>>(Wq,  wqh, wql);
  tsplit<<<tsg,tsb>>>(Wk,  wkh, wkl);
  tsplit<<<tsg,tsb>>>(Wv,  wvh, wvl);
  tsplit<<<tsg,tsb>>>(Wo,  woh, wol);

  split_hl<<<4096,256>>>(x, xh, xl);
  gemm_mma<<<gg,256,GEMM_SMEM>>>(xh, xl, wwh, wwl, W_b, h, 0);
  ln_split<<<8192,256>>>(h, lng, lnb, hh, hl);
  gemm_mma<<<gg,256,GEMM_SMEM>>>(hh, hl, wqh, wql, bq, q, 0);
  gemm_mma<<<gg,256,GEMM_SMEM>>>(hh, hl, wkh, wkl, bk, k, 0);
  gemm_mma<<<gg,256,GEMM_SMEM>>>(hh, hl, wvh, wvl, bv, v, 0);
  attn_kernel<<<dim3(8,8,16),256,ATTN_SMEM>>>(q, k, v, adj, ua, ctx);
  split_hl<<<4096,256>>>(ctx, ch, cl);
  gemm_mma<<<gg,256,GEMM_SMEM>>>(ch, cl, woh, wol, bo, h2, 1);
  gate_kernel<<<1024,256>>>(x, h2, gw, gbb, out);
}

// round 7
// speedup vs baseline: 1.4526x; 1.2369x over previous
#include <cuda_runtime.h>
#include <cuda_bf16.h>
#include <cstdint>

// Problem constants
#define MB 16
#define NT 512
#define DM 512
#define MROWS (MB*NT)   // 8192

// ---------------- scratch (static device arrays; no cudaMalloc allowed) ----
static __device__ float g_h  [MROWS*DM];
static __device__ float g_h2 [MROWS*DM];

// bf16 hi/lo splits
static __device__ __nv_bfloat16 g_xh[MROWS*DM], g_xl[MROWS*DM];
static __device__ __nv_bfloat16 g_hh[MROWS*DM], g_hl[MROWS*DM];
static __device__ __nv_bfloat16 g_qh[MROWS*DM], g_ql[MROWS*DM];
static __device__ __nv_bfloat16 g_kh[MROWS*DM], g_kl[MROWS*DM];
static __device__ __nv_bfloat16 g_vh[MROWS*DM], g_vl[MROWS*DM];
static __device__ __nv_bfloat16 g_ch[MROWS*DM], g_cl[MROWS*DM];
// bf16 hi/lo of transposed weights ([n,k] so D = A·B^T = A·W)
static __device__ __nv_bfloat16 g_wwh[DM*DM], g_wwl[DM*DM];
static __device__ __nv_bfloat16 g_wqh[DM*DM], g_wql[DM*DM];
static __device__ __nv_bfloat16 g_wkh[DM*DM], g_wkl[DM*DM];
static __device__ __nv_bfloat16 g_wvh[DM*DM], g_wvl[DM*DM];
static __device__ __nv_bfloat16 g_woh[DM*DM], g_wol[DM*DM];

__device__ __forceinline__ uint32_t s2u(const void* p){
  return (uint32_t)__cvta_generic_to_shared(p);
}

// ---------------- mma.sync helpers -----------------------------------------
__device__ __forceinline__ void ldsm4(uint32_t* r, uint32_t addr){
  asm volatile("ldmatrix.sync.aligned.m8n8.x4.shared.b16 {%0,%1,%2,%3}, [%4];"
   : "=r"(r[0]),"=r"(r[1]),"=r"(r[2]),"=r"(r[3]) : "r"(addr));
}
__device__ __forceinline__ void ldsm4t(uint32_t* r, uint32_t addr){
  asm volatile("ldmatrix.sync.aligned.m8n8.x4.trans.shared.b16 {%0,%1,%2,%3}, [%4];"
   : "=r"(r[0]),"=r"(r[1]),"=r"(r[2]),"=r"(r[3]) : "r"(addr));
}
__device__ __forceinline__ void mma16816(float* d, const uint32_t* a, const uint32_t* b){
  asm volatile("mma.sync.aligned.m16n8k16.row.col.f32.bf16.bf16.f32 "
    "{%0,%1,%2,%3}, {%4,%5,%6,%7}, {%8,%9}, {%0,%1,%2,%3};"
    : "+f"(d[0]),"+f"(d[1]),"+f"(d[2]),"+f"(d[3])
    : "r"(a[0]),"r"(a[1]),"r"(a[2]),"r"(a[3]), "r"(b[0]),"r"(b[1]));
}

// fast exp: fp32 accuracy ~2.4e-6, runs on fma/alu pipes (no MUFU)
__device__ __forceinline__ float fexp(float x){
  float y = x * 1.44269504f;
  int   ki = __float2int_rn(y);
  float f  = y - (float)ki;
  float p = 1.333355815e-3f;
  p = fmaf(p, f, 9.618129107e-3f);
  p = fmaf(p, f, 5.550410866e-2f);
  p = fmaf(p, f, 2.402265069e-1f);
  p = fmaf(p, f, 6.931471806e-1f);
  p = fmaf(p, f, 1.0f);
  return p * __int_as_float((ki + 127) << 23);
}

// ---------------- mma.sync GEMM: C[8192,512] = A @ W + bias ----------------
// 3 split terms (AhBh, AhBl, AlBh), CTA tile 128x128, BK=64, 8 warps, 2-stage.
// mode: 0 = fp32 out, 1 = fp32 + relu, 2 = bf16 hi/lo pair out
#define SA 72
#define ABYTES (128*SA*2)
#define STGB   (2*ABYTES)
#define GEMM_SMEM (2*STGB)

__global__ __launch_bounds__(256,2) void gemm_mma(
    const __nv_bfloat16* __restrict__ Ah, const __nv_bfloat16* __restrict__ Al,
    const __nv_bfloat16* __restrict__ Bh, const __nv_bfloat16* __restrict__ Bl,
    const float* __restrict__ bias, float* __restrict__ C,
    __nv_bfloat16* __restrict__ Ch, __nv_bfloat16* __restrict__ Cl, int mode)
{
  extern __shared__ __align__(16) char smem_raw[];
  const int tid  = threadIdx.x;
  const int lane = tid & 31, wid = tid >> 5;
  const int warpM = wid >> 1, warpN = wid & 1;
  const int m0 = blockIdx.y * 128;
  const int n0 = blockIdx.x * 128;

  float acc[2][8][4];
#pragma unroll
  for (int i=0;i<2;i++)
#pragma unroll
    for (int j=0;j<8;j++)
#pragma unroll
      for (int r=0;r<4;r++) acc[i][j][r]=0.f;

  const uint32_t sbase = s2u(smem_raw);
  const int ldRow = tid >> 1;
  const int ldSeg = (tid & 1) * 32;

  const uint32_t a_lane_off = (uint32_t)(((warpM*32 + (lane & 15)) * SA + (lane >> 4) * 8) * 2);
  const int n_off = ((lane >> 4) & 1) * 8 + (lane & 7);
  const int k_off = ((lane >> 3) & 1) * 8;
  uint32_t b_lane_off[4];
#pragma unroll
  for (int nip=0; nip<4; nip++)
    b_lane_off[nip] = (uint32_t)(((warpN*64 + nip*16 + n_off) * SA + k_off) * 2);

#define NC 24
#define LOAD_CHUNK(s, c) do { \
    const __nv_bfloat16* Asrc = ((c) >= 16) ? Al : Ah; \
    const __nv_bfloat16* Wsrc = ((c) >= 8 && (c) < 16) ? Bl : Bh; \
    const int kk0 = ((c) & 7) * 64; \
    uint32_t da = sbase + (s)*STGB + (uint32_t)((ldRow*SA + ldSeg)*2); \
    uint32_t dw = da + ABYTES; \
    const __nv_bfloat16* ga = Asrc + (size_t)(m0 + ldRow)*512 + kk0 + ldSeg; \
    const __nv_bfloat16* gw = Wsrc + (size_t)(n0 + ldRow)*512 + kk0 + ldSeg; \
    _Pragma("unroll") \
    for (int j=0;j<4;j++){ \
      asm volatile("cp.async.cg.shared.global [%0], [%1], 16;" :: "r"(da + j*16), "l"(ga + j*8)); \
      asm volatile("cp.async.cg.shared.global [%0], [%1], 16;" :: "r"(dw + j*16), "l"(gw + j*8)); \
    } \
  } while(0)

  LOAD_CHUNK(0, 0);
  asm volatile("cp.async.commit_group;" ::: "memory");

  for (int c=0; c<NC; c++){
    const int s = c & 1;
    if (c+1 < NC){
      LOAD_CHUNK(s^1, c+1);
      asm volatile("cp.async.commit_group;" ::: "memory");
      asm volatile("cp.async.wait_group 1;" ::: "memory");
    } else {
      asm volatile("cp.async.wait_group 0;" ::: "memory");
    }
    __syncthreads();

    const uint32_t abase = sbase + s*STGB + a_lane_off;
    const uint32_t bbase = sbase + s*STGB + ABYTES;
#pragma unroll
    for (int k16=0; k16<4; k16++){
      uint32_t af[2][4];
      ldsm4(af[0], abase + k16*32);
      ldsm4(af[1], abase + 16*SA*2 + k16*32);
#pragma unroll
      for (int nip=0; nip<4; nip++){
        uint32_t bf[4];
        ldsm4(bf, bbase + b_lane_off[nip] + k16*32);
        mma16816(acc[0][2*nip],   af[0], bf);
        mma16816(acc[0][2*nip+1], af[0], bf+2);
        mma16816(acc[1][2*nip],   af[1], bf);
        mma16816(acc[1][2*nip+1], af[1], bf+2);
      }
    }
    __syncthreads();
  }

  const int g  = lane >> 2;
  const int tg = lane & 3;
#pragma unroll
  for (int mi=0; mi<2; mi++){
    const int row = m0 + warpM*32 + mi*16 + g;
#pragma unroll
    for (int ni=0; ni<8; ni++){
      const int col = n0 + warpN*64 + ni*8 + tg*2;
      const float b0 = bias[col], b1 = bias[col+1];
      float v[4] = {acc[mi][ni][0]+b0, acc[mi][ni][1]+b1,
                    acc[mi][ni][2]+b0, acc[mi][ni][3]+b1};
      if (mode == 1){
#pragma unroll
        for (int e=0;e<4;e++) v[e] = fmaxf(v[e],0.f);
      }
      if (mode == 2){
        __nv_bfloat16 h0=__float2bfloat16(v[0]), h1=__float2bfloat16(v[1]);
        __nv_bfloat16 h2=__float2bfloat16(v[2]), h3=__float2bfloat16(v[3]);
        *reinterpret_cast<__nv_bfloat162*>(&Ch[(size_t)row*512+col]) =
            __halves2bfloat162(h0,h1);
        *reinterpret_cast<__nv_bfloat162*>(&Ch[(size_t)(row+8)*512+col]) =
            __halves2bfloat162(h2,h3);
        *reinterpret_cast<__nv_bfloat162*>(&Cl[(size_t)row*512+col]) =
            __halves2bfloat162(__float2bfloat16(v[0]-__bfloat162float(h0)),
                               __float2bfloat16(v[1]-__bfloat162float(h1)));
        *reinterpret_cast<__nv_bfloat162*>(&Cl[(size_t)(row+8)*512+col]) =
            __halves2bfloat162(__float2bfloat16(v[2]-__bfloat162float(h2)),
                               __float2bfloat16(v[3]-__bfloat162float(h3)));
      } else {
        *reinterpret_cast<float2*>(&C[(size_t)row*512 + col])     = make_float2(v[0],v[1]);
        *reinterpret_cast<float2*>(&C[(size_t)(row+8)*512 + col]) = make_float2(v[2],v[3]);
      }
    }
  }
}

// ---------------- fp32 -> bf16 hi/lo split ---------------------------------
__global__ void split_hl(const float* __restrict__ in,
                         __nv_bfloat16* __restrict__ hi,
                         __nv_bfloat16* __restrict__ lo)
{
  int i = blockIdx.x*256 + threadIdx.x;
  float4 v = reinterpret_cast<const float4*>(in)[i];
  float f[4] = {v.x, v.y, v.z, v.w};
  __nv_bfloat16 h[4], l[4];
#pragma unroll
  for (int j=0;j<4;j++){
    h[j] = __float2bfloat16(f[j]);
    l[j] = __float2bfloat16(f[j] - __bfloat162float(h[j]));
  }
  reinterpret_cast<__nv_bfloat162*>(hi)[2*i]   = __halves2bfloat162(h[0], h[1]);
  reinterpret_cast<__nv_bfloat162*>(hi)[2*i+1] = __halves2bfloat162(h[2], h[3]);
  reinterpret_cast<__nv_bfloat162*>(lo)[2*i]   = __halves2bfloat162(l[0], l[1]);
  reinterpret_cast<__nv_bfloat162*>(lo)[2*i+1] = __halves2bfloat162(l[2], l[3]);
}

// ---------------- W[512,512] -> transposed bf16 hi/lo [n,k] ----------------
__global__ void tsplit(const float* __restrict__ W,
                       __nv_bfloat16* __restrict__ Th,
                       __nv_bfloat16* __restrict__ Tl)
{
  __shared__ float t[32][33];
  const int bx = blockIdx.x*32;
  const int by = blockIdx.y*32;
  const int txx = threadIdx.x, tyy = threadIdx.y;
#pragma unroll
  for (int i=tyy;i<32;i+=8)
    t[i][txx] = W[(size_t)(by+i)*512 + bx + txx];
  __syncthreads();
#pragma unroll
  for (int i=tyy;i<32;i+=8){
    float v = t[txx][i];
    __nv_bfloat16 h = __float2bfloat16(v);
    __nv_bfloat16 l = __float2bfloat16(v - __bfloat162float(h));
    Th[(size_t)(bx+i)*512 + by + txx] = h;
    Tl[(size_t)(bx+i)*512 + by + txx] = l;
  }
}

// ---------------- LayerNorm + bf16 split -----------------------------------
__global__ void ln_split(const float* __restrict__ h, const float* __restrict__ g,
                         const float* __restrict__ b,
                         __nv_bfloat16* __restrict__ hh, __nv_bfloat16* __restrict__ hl)
{
  const int row = blockIdx.x;
  const int tid = threadIdx.x;
  const float* hr = h + (size_t)row*512;
  float v0 = hr[tid], v1 = hr[tid+256];
  __shared__ float red[8], red2[8];
  float s = v0+v1;
#pragma unroll
  for (int o=16;o;o>>=1) s += __shfl_xor_sync(0xffffffffu,s,o);
  if ((tid&31)==0) red[tid>>5]=s;
  __syncthreads();
  float mu = (red[0]+red[1]+red[2]+red[3]+red[4]+red[5]+red[6]+red[7]) * (1.f/512.f);
  float d0 = v0-mu, d1 = v1-mu;
  float q = d0*d0 + d1*d1;
#pragma unroll
  for (int o=16;o;o>>=1) q += __shfl_xor_sync(0xffffffffu,q,o);
  if ((tid&31)==0) red2[tid>>5]=q;
  __syncthreads();
  float var = (red2[0]+red2[1]+red2[2]+red2[3]+red2[4]+red2[5]+red2[6]+red2[7]) * (1.f/512.f);
  float rstd = rsqrtf(var + 1e-5f);
  float o0 = d0*rstd*g[tid]     + b[tid];
  float o1 = d1*rstd*g[tid+256] + b[tid+256];
  __nv_bfloat16 h0 = __float2bfloat16(o0);
  __nv_bfloat16 h1 = __float2bfloat16(o1);
  hh[(size_t)row*512 + tid]     = h0;
  hh[(size_t)row*512 + tid+256] = h1;
  hl[(size_t)row*512 + tid]     = __float2bfloat16(o0 - __bfloat162float(h0));
  hl[(size_t)row*512 + tid+256] = __float2bfloat16(o1 - __bfloat162float(h1));
}

// ---------------- Tensor-core flash attention (no-max softmax) -------------
// Per CTA: (b, h, 128 q rows). 256 threads, 8 warps (4 warpM x 2 warpN).
// S = QK^T via 3-term bf16 split mma; p = fexp(s*0.125*adj); P split hi/lo;
// O += P V via 3-term mma with ldmatrix.trans V. ctx written as bf16 hi/lo.
#define QB 144     // q/k/v smem row stride bytes (72 halves)
#define PB 272     // P smem row stride bytes (136 halves)
#define OQH 0
#define OQL 18432
#define OKH 36864
#define OKL 55296
#define OVH 73728
#define OVL 92160
#define OPH 110592
#define OPL 145408
#define OLP 180224
#define AT_SMEM (OLP + 1024)

__device__ __forceinline__ void at_load_tile(uint32_t sdst,
    const __nv_bfloat16* __restrict__ g, int row0, int col0, int tid)
{
  int row = tid >> 1, half = tid & 1;
  uint32_t d = sdst + (uint32_t)(row*QB + half*64);
  const __nv_bfloat16* s = g + (size_t)(row0+row)*512 + col0 + half*32;
#pragma unroll
  for (int j=0;j<4;j++)
    asm volatile("cp.async.cg.shared.global [%0], [%1], 16;" :: "r"(d + j*16), "l"(s + j*8));
}

__global__ __launch_bounds__(256,1) void attn_mma(
    const __nv_bfloat16* __restrict__ qh, const __nv_bfloat16* __restrict__ ql,
    const __nv_bfloat16* __restrict__ kh, const __nv_bfloat16* __restrict__ kl,
    const __nv_bfloat16* __restrict__ vh, const __nv_bfloat16* __restrict__ vl,
    const float* __restrict__ adj, const int* __restrict__ use_adj,
    __nv_bfloat16* __restrict__ ch, __nv_bfloat16* __restrict__ cl)
{
  extern __shared__ __align__(16) char sm8[];
  const uint32_t sb = s2u(sm8);
  float* lp = reinterpret_cast<float*>(sm8 + OLP);

  const int tid = threadIdx.x, lane = tid & 31, wid = tid >> 5;
  const int warpM = wid >> 1, warpN = wid & 1;
  const int q0 = blockIdx.x * 128;
  const int hh = blockIdx.y, bb = blockIdx.z;
  const int ua = use_adj[0];
  const int col0 = hh * 64;
  const int rowg0 = bb * 512;

  at_load_tile(sb+OQH, qh, rowg0+q0, col0, tid);
  at_load_tile(sb+OQL, ql, rowg0+q0, col0, tid);
  lp[tid] = 0.f;

  float oacc[2][4][4];
#pragma unroll
  for (int i=0;i<2;i++)
#pragma unroll
    for (int j=0;j<4;j++)
#pragma unroll
      for (int e=0;e<4;e++) oacc[i][j][e]=0.f;

  const uint32_t a_off  = (uint32_t)((lane&15)*QB + (lane>>4)*16);
  const uint32_t b_off  = (uint32_t)((((lane>>4)&1)*8 + (lane&7))*QB + ((lane>>3)&1)*16);
  const uint32_t ap_off = (uint32_t)((lane&15)*PB + (lane>>4)*16);

  const uint32_t qb_t[3] = {sb+OQH, sb+OQH, sb+OQL};
  const uint32_t kb_t[3] = {sb+OKH, sb+OKL, sb+OKH};
  const uint32_t pb_t[3] = {sb+OPH, sb+OPH, sb+OPL};
  const uint32_t vb_t[3] = {sb+OVH, sb+OVL, sb+OVH};

  const int r0 = warpM*32 + (lane>>2);
  const int cb = warpN*64 + 2*(lane&3);

  for (int kb=0; kb<4; kb++){
    const int krow0 = rowg0 + kb*128;
    if (kb == 0){
      at_load_tile(sb+OKH, kh, krow0, col0, tid);
      at_load_tile(sb+OKL, kl, krow0, col0, tid);
      at_load_tile(sb+OVH, vh, krow0, col0, tid);
      at_load_tile(sb+OVL, vl, krow0, col0, tid);
      asm volatile("cp.async.commit_group;" ::: "memory");
      asm volatile("cp.async.wait_group 0;" ::: "memory");
      __syncthreads();
    }

    // ---- S = Q K^T (3 terms) ----
    float sacc[2][8][4];
#pragma unroll
    for (int i=0;i<2;i++)
#pragma unroll
      for (int j=0;j<8;j++)
#pragma unroll
        for (int e=0;e<4;e++) sacc[i][j][e]=0.f;

#pragma unroll
    for (int t=0;t<3;t++){
      const uint32_t qb_ = qb_t[t] + (uint32_t)(warpM*32*QB) + a_off;
      const uint32_t kb_ = kb_t[t] + (uint32_t)(warpN*64*QB) + b_off;
#pragma unroll
      for (int k16=0;k16<4;k16++){
        uint32_t af[2][4];
        ldsm4(af[0], qb_ + k16*32);
        ldsm4(af[1], qb_ + 16*QB + k16*32);
#pragma unroll
        for (int nf=0;nf<4;nf++){
          uint32_t bf[4];
          ldsm4(bf, kb_ + (uint32_t)(nf*16*QB) + k16*32);
          mma16816(sacc[0][2*nf],   af[0], bf);
          mma16816(sacc[0][2*nf+1], af[0], bf+2);
          mma16816(sacc[1][2*nf],   af[1], bf);
          mma16816(sacc[1][2*nf+1], af[1], bf+2);
        }
      }
    }

    // ---- scale*adj, exp, row sums, store P hi/lo ----
#pragma unroll
    for (int mi=0;mi<2;mi++){
      const int rr = r0 + mi*16;
      float rs0 = 0.f, rs8 = 0.f;
#pragma unroll
      for (int nf=0;nf<8;nf++){
        const int cc = cb + nf*8;
        float m0=1.f,m1=1.f,m2=1.f,m3=1.f;
        if (ua){
          const float* ar = adj + ((size_t)(rowg0+q0+rr))*512 + kb*128 + cc;
          float2 a01 = *reinterpret_cast<const float2*>(ar);
          float2 a23 = *reinterpret_cast<const float2*>(ar + 8*512);
          m0=a01.x; m1=a01.y; m2=a23.x; m3=a23.y;
        }
        float p0 = fexp(sacc[mi][nf][0]*0.125f*m0);
        float p1 = fexp(sacc[mi][nf][1]*0.125f*m1);
        float p2 = fexp(sacc[mi][nf][2]*0.125f*m2);
        float p3 = fexp(sacc[mi][nf][3]*0.125f*m3);
        rs0 += p0+p1;  rs8 += p2+p3;
        __nv_bfloat16 h0=__float2bfloat16(p0), h1=__float2bfloat16(p1);
        __nv_bfloat16 h2=__float2bfloat16(p2), h3=__float2bfloat16(p3);
        uint32_t ph01, ph23, pl01, pl23;
        {
          __nv_bfloat162 t0 = __halves2bfloat162(h0,h1);
          __nv_bfloat162 t1 = __halves2bfloat162(h2,h3);
          __nv_bfloat162 t2 = __halves2bfloat162(__float2bfloat16(p0-__bfloat162float(h0)),
                                                 __float2bfloat16(p1-__bfloat162float(h1)));
          __nv_bfloat162 t3 = __halves2bfloat162(__float2bfloat16(p2-__bfloat162float(h2)),
                                                 __float2bfloat16(p3-__bfloat162float(h3)));
          ph01 = *reinterpret_cast<uint32_t*>(&t0);
          ph23 = *reinterpret_cast<uint32_t*>(&t1);
          pl01 = *reinterpret_cast<uint32_t*>(&t2);
          pl23 = *reinterpret_cast<uint32_t*>(&t3);
        }
        uint32_t pa = sb + OPH + (uint32_t)(rr*PB + cc*2);
        uint32_t pb_ = sb + OPL + (uint32_t)(rr*PB + cc*2);
        asm volatile("st.shared.b32 [%0], %1;" :: "r"(pa), "r"(ph01));
        asm volatile("st.shared.b32 [%0], %1;" :: "r"(pa + 8*PB), "r"(ph23));
        asm volatile("st.shared.b32 [%0], %1;" :: "r"(pb_), "r"(pl01));
        asm volatile("st.shared.b32 [%0], %1;" :: "r"(pb_ + 8*PB), "r"(pl23));
      }
      rs0 += __shfl_xor_sync(0xffffffffu, rs0, 1);
      rs0 += __shfl_xor_sync(0xffffffffu, rs0, 2);
      rs8 += __shfl_xor_sync(0xffffffffu, rs8, 1);
      rs8 += __shfl_xor_sync(0xffffffffu, rs8, 2);
      if ((lane&3)==0){
        lp[warpN*128 + rr]     += rs0;
        lp[warpN*128 + rr + 8] += rs8;
      }
    }
    __syncthreads();   // K reads + P writes complete

    if (kb < 3){       // prefetch next K while PV runs
      at_load_tile(sb+OKH, kh, krow0+128, col0, tid);
      at_load_tile(sb+OKL, kl, krow0+128, col0, tid);
      asm volatile("cp.async.commit_group;" ::: "memory");
    }

    // ---- O += P V (3 terms), V^T via ldmatrix.trans ----
#pragma unroll
    for (int t=0;t<3;t++){
      const uint32_t pb2 = pb_t[t] + (uint32_t)(warpM*32*PB) + ap_off;
      const uint32_t vb2 = vb_t[t] + (uint32_t)((lane&15)*QB + (warpN*32 + (lane>>4)*8)*2);
#pragma unroll
      for (int k16=0;k16<8;k16++){
        uint32_t af[2][4];
        ldsm4(af[0], pb2 + k16*32);
        ldsm4(af[1], pb2 + 16*PB + k16*32);
#pragma unroll
        for (int nf=0;nf<2;nf++){
          uint32_t bf[4];
          ldsm4t(bf, vb2 + (uint32_t)(k16*16*QB) + (uint32_t)(nf*16*2));
          mma16816(oacc[0][2*nf],   af[0], bf);
          mma16816(oacc[0][2*nf+1], af[0], bf+2);
          mma16816(oacc[1][2*nf],   af[1], bf);
          mma16816(oacc[1][2*nf+1], af[1], bf+2);
        }
      }
    }
    __syncthreads();   // V reads complete

    if (kb < 3){
      at_load_tile(sb+OVH, vh, krow0+128, col0, tid);
      at_load_tile(sb+OVL, vl, krow0+128, col0, tid);
      asm volatile("cp.async.commit_group;" ::: "memory");
      asm volatile("cp.async.wait_group 0;" ::: "memory");
      __syncthreads();
    }
  }

  // ---- epilogue: normalize, split, store ----
  if (tid < 128) lp[tid] = 1.f / (lp[tid] + lp[128 + tid]);
  __syncthreads();
#pragma unroll
  for (int mi=0;mi<2;mi++){
    const int rr = r0 + mi*16;
    const float inv0 = lp[rr], inv8 = lp[rr+8];
    const size_t rga = (size_t)(rowg0 + q0 + rr);
#pragma unroll
    for (int nf=0;nf<4;nf++){
      const int colg = col0 + warpN*32 + nf*8 + 2*(lane&3);
      float c0 = oacc[mi][nf][0]*inv0, c1 = oacc[mi][nf][1]*inv0;
      float c2 = oacc[mi][nf][2]*inv8, c3 = oacc[mi][nf][3]*inv8;
      __nv_bfloat16 h0=__float2bfloat16(c0), h1=__float2bfloat16(c1);
      __nv_bfloat16 h2=__float2bfloat16(c2), h3=__float2bfloat16(c3);
      *reinterpret_cast<__nv_bfloat162*>(&ch[rga*512 + colg]) = __halves2bfloat162(h0,h1);
      *reinterpret_cast<__nv_bfloat162*>(&ch[(rga+8)*512 + colg]) = __halves2bfloat162(h2,h3);
      *reinterpret_cast<__nv_bfloat162*>(&cl[rga*512 + colg]) =
          __halves2bfloat162(__float2bfloat16(c0-__bfloat162float(h0)),
                             __float2bfloat16(c1-__bfloat162float(h1)));
      *reinterpret_cast<__nv_bfloat162*>(&cl[(rga+8)*512 + colg]) =
          __halves2bfloat162(__float2bfloat16(c2-__bfloat162float(h2)),
                             __float2bfloat16(c3-__bfloat162float(h3)));
    }
  }
}

// ---------------- Gate + blend: out = c*x + (1-c)*h2 -----------------------
__global__ void gate_kernel(const float* __restrict__ x, const float* __restrict__ h2,
    const float* __restrict__ gw, const float* __restrict__ gb, float* __restrict__ out)
{
  const int w = threadIdx.x>>5, lane = threadIdx.x&31;
  const int row = blockIdx.x*8 + w;
  const float* xr = x  + (size_t)row*512;
  const float* hr = h2 + (size_t)row*512;
  float s = 0.f;
#pragma unroll
  for (int i=0;i<16;i++){
    int c = i*32 + lane;
    s += xr[c]*gw[c] + hr[c]*gw[512+c];
  }
#pragma unroll
  for (int off=16;off;off>>=1) s += __shfl_xor_sync(0xffffffffu,s,off);
  s += gb[0];
  float coeff = 1.f/(1.f+__expf(-s));
  float* orow = out + (size_t)row*512;
#pragma unroll
  for (int i=0;i<16;i++){
    int c = i*32+lane;
    orow[c] = coeff*xr[c] + (1.f-coeff)*hr[c];
  }
}

// ---------------- launch ---------------------------------------------------
extern "C" void kernel_launch(void* const* d_in, const int* in_sizes, int n_in,
                              void* d_out, int out_size)
{
  const float* x   = (const float*)d_in[0];
  const float* adj = (const float*)d_in[1];
  const float* W_w = (const float*)d_in[2];
  const float* W_b = (const float*)d_in[3];
  const float* lng = (const float*)d_in[4];
  const float* lnb = (const float*)d_in[5];
  const float* Wq  = (const float*)d_in[6];
  const float* bq  = (const float*)d_in[7];
  const float* Wk  = (const float*)d_in[8];
  const float* bk  = (const float*)d_in[9];
  const float* Wv  = (const float*)d_in[10];
  const float* bv  = (const float*)d_in[11];
  const float* Wo  = (const float*)d_in[12];
  const float* bo  = (const float*)d_in[13];
  const float* gw  = (const float*)d_in[14];
  const float* gbb = (const float*)d_in[15];
  const int*   ua  = (const int*)d_in[16];
  float* out = (float*)d_out;

  float *h,*h2;
  cudaGetSymbolAddress((void**)&h,   g_h);
  cudaGetSymbolAddress((void**)&h2,  g_h2);

  __nv_bfloat16 *xh,*xl,*hh,*hl,*qh,*ql,*kh,*kl,*vh,*vl,*ch,*cl;
  __nv_bfloat16 *wwh,*wwl,*wqh,*wql,*wkh,*wkl,*wvh,*wvl,*woh,*wol;
  cudaGetSymbolAddress((void**)&xh, g_xh);  cudaGetSymbolAddress((void**)&xl, g_xl);
  cudaGetSymbolAddress((void**)&hh, g_hh);  cudaGetSymbolAddress((void**)&hl, g_hl);
  cudaGetSymbolAddress((void**)&qh, g_qh);  cudaGetSymbolAddress((void**)&ql, g_ql);
  cudaGetSymbolAddress((void**)&kh, g_kh);  cudaGetSymbolAddress((void**)&kl, g_kl);
  cudaGetSymbolAddress((void**)&vh, g_vh);  cudaGetSymbolAddress((void**)&vl, g_vl);
  cudaGetSymbolAddress((void**)&ch, g_ch);  cudaGetSymbolAddress((void**)&cl, g_cl);
  cudaGetSymbolAddress((void**)&wwh, g_wwh); cudaGetSymbolAddress((void**)&wwl, g_wwl);
  cudaGetSymbolAddress((void**)&wqh, g_wqh); cudaGetSymbolAddress((void**)&wql, g_wql);
  cudaGetSymbolAddress((void**)&wkh, g_wkh); cudaGetSymbolAddress((void**)&wkl, g_wkl);
  cudaGetSymbolAddress((void**)&wvh, g_wvh); cudaGetSymbolAddress((void**)&wvl, g_wvl);
  cudaGetSymbolAddress((void**)&woh, g_woh); cudaGetSymbolAddress((void**)&wol, g_wol);

  cudaFuncSetAttribute(gemm_mma, cudaFuncAttributeMaxDynamicSharedMemorySize, GEMM_SMEM);
  cudaFuncSetAttribute(attn_mma, cudaFuncAttributeMaxDynamicSharedMemorySize, AT_SMEM);

  dim3 tsg(16,16), tsb(32,8);
  dim3 gg(4,64);

  tsplit<<<tsg,tsb>>>(W_w, wwh, wwl);                                   // 0
  split_hl<<<4096,256>>>(x, xh, xl);                                    // 1
  gemm_mma<<<gg,256,GEMM_SMEM>>>(xh,xl,wwh,wwl,W_b,h,0,0,0);            // 2
  ln_split<<<8192,256>>>(h, lng, lnb, hh, hl);                          // 3
  tsplit<<<tsg,tsb>>>(Wq, wqh, wql);                                    // 4
  gemm_mma<<<gg,256,GEMM_SMEM>>>(hh,hl,wqh,wql,bq,0,qh,ql,2);           // 5 (ncu)
  tsplit<<<tsg,tsb>>>(Wk, wkh, wkl);                                    // 6
  gemm_mma<<<gg,256,GEMM_SMEM>>>(hh,hl,wkh,wkl,bk,0,kh,kl,2);           // 7
  tsplit<<<tsg,tsb>>>(Wv, wvh, wvl);                                    // 8
  gemm_mma<<<gg,256,GEMM_SMEM>>>(hh,hl,wvh,wvl,bv,0,vh,vl,2);           // 9
  tsplit<<<tsg,tsb>>>(Wo, woh, wol);                                    // 10
  attn_mma<<<dim3(4,8,16),256,AT_SMEM>>>(qh,ql,kh,kl,vh,vl,adj,ua,ch,cl); // 11
  gemm_mma<<<gg,256,GEMM_SMEM>>>(ch,cl,woh,wol,bo,h2,0,0,1);            // 12
  gate_kernel<<<1024,256>>>(x, h2, gw, gbb, out);                       // 13
}

// round 8
// speedup vs baseline: 1.4998x; 1.0325x over previous
#include <cuda_runtime.h>
#include <cuda_bf16.h>
#include <cstdint>

// Problem constants
#define MB 16
#define NT 512
#define DM 512
#define MROWS (MB*NT)   // 8192

// ---------------- scratch (static device arrays; no cudaMalloc allowed) ----
static __device__ float g_h  [MROWS*DM];
static __device__ float g_h2 [MROWS*DM];

// bf16 hi/lo splits
static __device__ __nv_bfloat16 g_xh[MROWS*DM], g_xl[MROWS*DM];
static __device__ __nv_bfloat16 g_hh[MROWS*DM], g_hl[MROWS*DM];
static __device__ __nv_bfloat16 g_qh[MROWS*DM], g_ql[MROWS*DM];
static __device__ __nv_bfloat16 g_kh[MROWS*DM], g_kl[MROWS*DM];
static __device__ __nv_bfloat16 g_vh[MROWS*DM], g_vl[MROWS*DM];
static __device__ __nv_bfloat16 g_ch[MROWS*DM], g_cl[MROWS*DM];
// bf16 hi/lo of transposed weights ([n,k] so D = A·B^T = A·W)
static __device__ __nv_bfloat16 g_wwh[DM*DM], g_wwl[DM*DM];
static __device__ __nv_bfloat16 g_wqh[DM*DM], g_wql[DM*DM];
static __device__ __nv_bfloat16 g_wkh[DM*DM], g_wkl[DM*DM];
static __device__ __nv_bfloat16 g_wvh[DM*DM], g_wvl[DM*DM];
static __device__ __nv_bfloat16 g_woh[DM*DM], g_wol[DM*DM];

__device__ __forceinline__ uint32_t s2u(const void* p){
  return (uint32_t)__cvta_generic_to_shared(p);
}

// ---------------- mma.sync helpers -----------------------------------------
__device__ __forceinline__ void ldsm4(uint32_t* r, uint32_t addr){
  asm volatile("ldmatrix.sync.aligned.m8n8.x4.shared.b16 {%0,%1,%2,%3}, [%4];"
   : "=r"(r[0]),"=r"(r[1]),"=r"(r[2]),"=r"(r[3]) : "r"(addr));
}
__device__ __forceinline__ void ldsm4t(uint32_t* r, uint32_t addr){
  asm volatile("ldmatrix.sync.aligned.m8n8.x4.trans.shared.b16 {%0,%1,%2,%3}, [%4];"
   : "=r"(r[0]),"=r"(r[1]),"=r"(r[2]),"=r"(r[3]) : "r"(addr));
}
__device__ __forceinline__ void mma16816(float* d, const uint32_t* a, const uint32_t* b){
  asm volatile("mma.sync.aligned.m16n8k16.row.col.f32.bf16.bf16.f32 "
    "{%0,%1,%2,%3}, {%4,%5,%6,%7}, {%8,%9}, {%0,%1,%2,%3};"
    : "+f"(d[0]),"+f"(d[1]),"+f"(d[2]),"+f"(d[3])
    : "r"(a[0]),"r"(a[1]),"r"(a[2]),"r"(a[3]), "r"(b[0]),"r"(b[1]));
}

// fast exp: fp32 accuracy ~2.4e-6, runs on fma/alu pipes (no MUFU)
__device__ __forceinline__ float fexp(float x){
  float y = x * 1.44269504f;
  int   ki = __float2int_rn(y);
  float f  = y - (float)ki;
  float p = 1.333355815e-3f;
  p = fmaf(p, f, 9.618129107e-3f);
  p = fmaf(p, f, 5.550410866e-2f);
  p = fmaf(p, f, 2.402265069e-1f);
  p = fmaf(p, f, 6.931471806e-1f);
  p = fmaf(p, f, 1.0f);
  return p * __int_as_float((ki + 127) << 23);
}

// ---------------- GEMM core (3-stage ring, 1 sync/chunk) --------------------
// C[8192,512] = A @ W^T(+bias). 3 split terms, CTA tile 128x128, BK=64, 8 warps.
#define SA 72
#define ABYTES (128*SA*2)
#define STGB   (2*ABYTES)            // 36864
#define NSTG 3
#define GEMM_SMEM (NSTG*STGB)        // 110592
#define NC 24

struct GemmCore {
  uint32_t sbase;
  int m0, n0, tid, lane, warpM, warpN;
  float acc[2][8][4];

  __device__ __forceinline__ void init(uint32_t sb, int m0_, int n0_){
    sbase = sb; m0 = m0_; n0 = n0_;
    tid = threadIdx.x; lane = tid & 31;
    int wid = tid >> 5; warpM = wid >> 1; warpN = wid & 1;
#pragma unroll
    for (int i=0;i<2;i++)
#pragma unroll
      for (int j=0;j<8;j++)
#pragma unroll
        for (int r=0;r<4;r++) acc[i][j][r]=0.f;
  }

  __device__ __forceinline__ void load_chunk(int s, int c,
      const __nv_bfloat16* Ah, const __nv_bfloat16* Al,
      const __nv_bfloat16* Bh, const __nv_bfloat16* Bl){
    const __nv_bfloat16* Asrc = (c >= 16) ? Al : Ah;
    const __nv_bfloat16* Wsrc = (c >= 8 && c < 16) ? Bl : Bh;
    const int kk0 = (c & 7) * 64;
    const int ldRow = tid >> 1;
    const int ldSeg = (tid & 1) * 32;
    uint32_t da = sbase + s*STGB + (uint32_t)((ldRow*SA + ldSeg)*2);
    uint32_t dw = da + ABYTES;
    const __nv_bfloat16* ga = Asrc + (size_t)(m0 + ldRow)*512 + kk0 + ldSeg;
    const __nv_bfloat16* gw = Wsrc + (size_t)(n0 + ldRow)*512 + kk0 + ldSeg;
#pragma unroll
    for (int j=0;j<4;j++){
      asm volatile("cp.async.cg.shared.global [%0], [%1], 16;" :: "r"(da + j*16), "l"(ga + j*8));
      asm volatile("cp.async.cg.shared.global [%0], [%1], 16;" :: "r"(dw + j*16), "l"(gw + j*8));
    }
    asm volatile("cp.async.commit_group;" ::: "memory");
  }

  __device__ __forceinline__ void compute(int s){
    const uint32_t a_lane_off = (uint32_t)(((warpM*32 + (lane & 15)) * SA + (lane >> 4) * 8) * 2);
    const int n_off = ((lane >> 4) & 1) * 8 + (lane & 7);
    const int k_off = ((lane >> 3) & 1) * 8;
    const uint32_t abase = sbase + s*STGB + a_lane_off;
    const uint32_t bbase = sbase + s*STGB + ABYTES;
#pragma unroll
    for (int k16=0; k16<4; k16++){
      uint32_t af[2][4];
      ldsm4(af[0], abase + k16*32);
      ldsm4(af[1], abase + 16*SA*2 + k16*32);
#pragma unroll
      for (int nip=0; nip<4; nip++){
        uint32_t bf[4];
        uint32_t boff = (uint32_t)(((warpN*64 + nip*16 + n_off) * SA + k_off) * 2);
        ldsm4(bf, bbase + boff + k16*32);
        mma16816(acc[0][2*nip],   af[0], bf);
        mma16816(acc[0][2*nip+1], af[0], bf+2);
        mma16816(acc[1][2*nip],   af[1], bf);
        mma16816(acc[1][2*nip+1], af[1], bf+2);
      }
    }
  }

  __device__ __forceinline__ void run(
      const __nv_bfloat16* Ah, const __nv_bfloat16* Al,
      const __nv_bfloat16* Bh, const __nv_bfloat16* Bl){
    load_chunk(0, 0, Ah, Al, Bh, Bl);
    load_chunk(1, 1, Ah, Al, Bh, Bl);
    for (int c=0; c<NC; c++){
      if (c < NC-1) asm volatile("cp.async.wait_group 1;" ::: "memory");
      else          asm volatile("cp.async.wait_group 0;" ::: "memory");
      __syncthreads();
      if (c+2 < NC) load_chunk((c+2)%NSTG, c+2, Ah, Al, Bh, Bl);
      compute(c%NSTG);
    }
  }

  // mode: 0 fp32, 1 fp32+relu, 2 bf16 hi/lo
  __device__ __forceinline__ void epilogue(const float* bias, float* C,
      __nv_bfloat16* Ch, __nv_bfloat16* Cl, int mode){
    const int g  = lane >> 2;
    const int tg = lane & 3;
#pragma unroll
    for (int mi=0; mi<2; mi++){
      const int row = m0 + warpM*32 + mi*16 + g;
#pragma unroll
      for (int ni=0; ni<8; ni++){
        const int col = n0 + warpN*64 + ni*8 + tg*2;
        const float b0 = bias[col & 511], b1 = bias[(col & 511)+1];
        float v[4] = {acc[mi][ni][0]+b0, acc[mi][ni][1]+b1,
                      acc[mi][ni][2]+b0, acc[mi][ni][3]+b1};
        if (mode == 1){
#pragma unroll
          for (int e=0;e<4;e++) v[e] = fmaxf(v[e],0.f);
        }
        if (mode == 2){
          const int ocol = col & 511;
          __nv_bfloat16 h0=__float2bfloat16(v[0]), h1=__float2bfloat16(v[1]);
          __nv_bfloat16 h2=__float2bfloat16(v[2]), h3=__float2bfloat16(v[3]);
          *reinterpret_cast<__nv_bfloat162*>(&Ch[(size_t)row*512+ocol]) =
              __halves2bfloat162(h0,h1);
          *reinterpret_cast<__nv_bfloat162*>(&Ch[(size_t)(row+8)*512+ocol]) =
              __halves2bfloat162(h2,h3);
          *reinterpret_cast<__nv_bfloat162*>(&Cl[(size_t)row*512+ocol]) =
              __halves2bfloat162(__float2bfloat16(v[0]-__bfloat162float(h0)),
                                 __float2bfloat16(v[1]-__bfloat162float(h1)));
          *reinterpret_cast<__nv_bfloat162*>(&Cl[(size_t)(row+8)*512+ocol]) =
              __halves2bfloat162(__float2bfloat16(v[2]-__bfloat162float(h2)),
                                 __float2bfloat16(v[3]-__bfloat162float(h3)));
        } else {
          *reinterpret_cast<float2*>(&C[(size_t)row*512 + col])     = make_float2(v[0],v[1]);
          *reinterpret_cast<float2*>(&C[(size_t)(row+8)*512 + col]) = make_float2(v[2],v[3]);
        }
      }
    }
  }
};

__global__ __launch_bounds__(256,2) void gemm_mma(
    const __nv_bfloat16* __restrict__ Ah, const __nv_bfloat16* __restrict__ Al,
    const __nv_bfloat16* __restrict__ Bh, const __nv_bfloat16* __restrict__ Bl,
    const float* __restrict__ bias, float* __restrict__ C,
    __nv_bfloat16* __restrict__ Ch, __nv_bfloat16* __restrict__ Cl, int mode)
{
  extern __shared__ __align__(16) char smem_raw[];
  GemmCore core;
  core.init(s2u(smem_raw), blockIdx.y*128, blockIdx.x*128);
  core.run(Ah, Al, Bh, Bl);
  core.epilogue(bias, C, Ch, Cl, mode);
}

// Fused QKV: grid (12, 64); weight = blockIdx.x>>2, n-tile = blockIdx.x&3.
struct QKVArgs {
  const __nv_bfloat16 *bh0,*bl0,*bh1,*bl1,*bh2,*bl2;
  const float *bias0,*bias1,*bias2;
  __nv_bfloat16 *ch0,*cl0,*ch1,*cl1,*ch2,*cl2;
};

__global__ __launch_bounds__(256,2) void gemm_qkv(
    const __nv_bfloat16* __restrict__ Ah, const __nv_bfloat16* __restrict__ Al,
    QKVArgs a)
{
  extern __shared__ __align__(16) char smem_raw[];
  const int w = blockIdx.x >> 2;
  const __nv_bfloat16* Bh = (w==0) ? a.bh0 : (w==1) ? a.bh1 : a.bh2;
  const __nv_bfloat16* Bl = (w==0) ? a.bl0 : (w==1) ? a.bl1 : a.bl2;
  const float* bias       = (w==0) ? a.bias0 : (w==1) ? a.bias1 : a.bias2;
  __nv_bfloat16* Ch       = (w==0) ? a.ch0 : (w==1) ? a.ch1 : a.ch2;
  __nv_bfloat16* Cl       = (w==0) ? a.cl0 : (w==1) ? a.cl1 : a.cl2;
  GemmCore core;
  core.init(s2u(smem_raw), blockIdx.y*128, (blockIdx.x & 3)*128);
  core.run(Ah, Al, Bh, Bl);
  core.epilogue(bias, 0, Ch, Cl, 2);
}

// ---------------- fp32 -> bf16 hi/lo split ---------------------------------
__global__ void split_hl(const float* __restrict__ in,
                         __nv_bfloat16* __restrict__ hi,
                         __nv_bfloat16* __restrict__ lo)
{
  int i = blockIdx.x*256 + threadIdx.x;
  float4 v = reinterpret_cast<const float4*>(in)[i];
  float f[4] = {v.x, v.y, v.z, v.w};
  __nv_bfloat16 h[4], l[4];
#pragma unroll
  for (int j=0;j<4;j++){
    h[j] = __float2bfloat16(f[j]);
    l[j] = __float2bfloat16(f[j] - __bfloat162float(h[j]));
  }
  reinterpret_cast<__nv_bfloat162*>(hi)[2*i]   = __halves2bfloat162(h[0], h[1]);
  reinterpret_cast<__nv_bfloat162*>(hi)[2*i+1] = __halves2bfloat162(h[2], h[3]);
  reinterpret_cast<__nv_bfloat162*>(lo)[2*i]   = __halves2bfloat162(l[0], l[1]);
  reinterpret_cast<__nv_bfloat162*>(lo)[2*i+1] = __halves2bfloat162(l[2], l[3]);
}

// ---------------- W[512,512] -> transposed bf16 hi/lo [n,k] ----------------
__global__ void tsplit(const float* __restrict__ W,
                       __nv_bfloat16* __restrict__ Th,
                       __nv_bfloat16* __restrict__ Tl)
{
  __shared__ float t[32][33];
  const int bx = blockIdx.x*32;
  const int by = blockIdx.y*32;
  const int txx = threadIdx.x, tyy = threadIdx.y;
#pragma unroll
  for (int i=tyy;i<32;i+=8)
    t[i][txx] = W[(size_t)(by+i)*512 + bx + txx];
  __syncthreads();
#pragma unroll
  for (int i=tyy;i<32;i+=8){
    float v = t[txx][i];
    __nv_bfloat16 h = __float2bfloat16(v);
    __nv_bfloat16 l = __float2bfloat16(v - __bfloat162float(h));
    Th[(size_t)(bx+i)*512 + by + txx] = h;
    Tl[(size_t)(bx+i)*512 + by + txx] = l;
  }
}

// ---------------- LayerNorm + bf16 split -----------------------------------
__global__ void ln_split(const float* __restrict__ h, const float* __restrict__ g,
                         const float* __restrict__ b,
                         __nv_bfloat16* __restrict__ hh, __nv_bfloat16* __restrict__ hl)
{
  const int row = blockIdx.x;
  const int tid = threadIdx.x;
  const float* hr = h + (size_t)row*512;
  float v0 = hr[tid], v1 = hr[tid+256];
  __shared__ float red[8], red2[8];
  float s = v0+v1;
#pragma unroll
  for (int o=16;o;o>>=1) s += __shfl_xor_sync(0xffffffffu,s,o);
  if ((tid&31)==0) red[tid>>5]=s;
  __syncthreads();
  float mu = (red[0]+red[1]+red[2]+red[3]+red[4]+red[5]+red[6]+red[7]) * (1.f/512.f);
  float d0 = v0-mu, d1 = v1-mu;
  float q = d0*d0 + d1*d1;
#pragma unroll
  for (int o=16;o;o>>=1) q += __shfl_xor_sync(0xffffffffu,q,o);
  if ((tid&31)==0) red2[tid>>5]=q;
  __syncthreads();
  float var = (red2[0]+red2[1]+red2[2]+red2[3]+red2[4]+red2[5]+red2[6]+red2[7]) * (1.f/512.f);
  float rstd = rsqrtf(var + 1e-5f);
  float o0 = d0*rstd*g[tid]     + b[tid];
  float o1 = d1*rstd*g[tid+256] + b[tid+256];
  __nv_bfloat16 h0 = __float2bfloat16(o0);
  __nv_bfloat16 h1 = __float2bfloat16(o1);
  hh[(size_t)row*512 + tid]     = h0;
  hh[(size_t)row*512 + tid+256] = h1;
  hl[(size_t)row*512 + tid]     = __float2bfloat16(o0 - __bfloat162float(h0));
  hl[(size_t)row*512 + tid+256] = __float2bfloat16(o1 - __bfloat162float(h1));
}

// ---------------- Tensor-core flash attention (no-max softmax) -------------
#define QB 144
#define PB 272
#define OQH 0
#define OQL 18432
#define OKH 36864
#define OKL 55296
#define OVH 73728
#define OVL 92160
#define OPH 110592
#define OPL 145408
#define OLP 180224
#define AT_SMEM (OLP + 1024)

__device__ __forceinline__ void at_load_tile(uint32_t sdst,
    const __nv_bfloat16* __restrict__ g, int row0, int col0, int tid)
{
  int row = tid >> 1, half = tid & 1;
  uint32_t d = sdst + (uint32_t)(row*QB + half*64);
  const __nv_bfloat16* s = g + (size_t)(row0+row)*512 + col0 + half*32;
#pragma unroll
  for (int j=0;j<4;j++)
    asm volatile("cp.async.cg.shared.global [%0], [%1], 16;" :: "r"(d + j*16), "l"(s + j*8));
}

__global__ __launch_bounds__(256,1) void attn_mma(
    const __nv_bfloat16* __restrict__ qh, const __nv_bfloat16* __restrict__ ql,
    const __nv_bfloat16* __restrict__ kh, const __nv_bfloat16* __restrict__ kl,
    const __nv_bfloat16* __restrict__ vh, const __nv_bfloat16* __restrict__ vl,
    const float* __restrict__ adj, const int* __restrict__ use_adj,
    __nv_bfloat16* __restrict__ ch, __nv_bfloat16* __restrict__ cl)
{
  extern __shared__ __align__(16) char sm8[];
  const uint32_t sb = s2u(sm8);
  float* lp = reinterpret_cast<float*>(sm8 + OLP);

  const int tid = threadIdx.x, lane = tid & 31, wid = tid >> 5;
  const int warpM = wid >> 1, warpN = wid & 1;
  const int q0 = blockIdx.x * 128;
  const int hh = blockIdx.y, bb = blockIdx.z;
  const int ua = use_adj[0];
  const int col0 = hh * 64;
  const int rowg0 = bb * 512;

  at_load_tile(sb+OQH, qh, rowg0+q0, col0, tid);
  at_load_tile(sb+OQL, ql, rowg0+q0, col0, tid);
  lp[tid] = 0.f;

  float oacc[2][4][4];
#pragma unroll
  for (int i=0;i<2;i++)
#pragma unroll
    for (int j=0;j<4;j++)
#pragma unroll
      for (int e=0;e<4;e++) oacc[i][j][e]=0.f;

  const uint32_t a_off  = (uint32_t)((lane&15)*QB + (lane>>4)*16);
  const uint32_t b_off  = (uint32_t)((((lane>>4)&1)*8 + (lane&7))*QB + ((lane>>3)&1)*16);
  const uint32_t ap_off = (uint32_t)((lane&15)*PB + (lane>>4)*16);

  const uint32_t qb_t[3] = {sb+OQH, sb+OQH, sb+OQL};
  const uint32_t kb_t[3] = {sb+OKH, sb+OKL, sb+OKH};
  const uint32_t pb_t[3] = {sb+OPH, sb+OPH, sb+OPL};
  const uint32_t vb_t[3] = {sb+OVH, sb+OVL, sb+OVH};

  const int r0 = warpM*32 + (lane>>2);
  const int cb = warpN*64 + 2*(lane&3);

  for (int kb=0; kb<4; kb++){
    const int krow0 = rowg0 + kb*128;
    if (kb == 0){
      at_load_tile(sb+OKH, kh, krow0, col0, tid);
      at_load_tile(sb+OKL, kl, krow0, col0, tid);
      at_load_tile(sb+OVH, vh, krow0, col0, tid);
      at_load_tile(sb+OVL, vl, krow0, col0, tid);
      asm volatile("cp.async.commit_group;" ::: "memory");
      asm volatile("cp.async.wait_group 0;" ::: "memory");
      __syncthreads();
    }

    // ---- S = Q K^T (3 terms) ----
    float sacc[2][8][4];
#pragma unroll
    for (int i=0;i<2;i++)
#pragma unroll
      for (int j=0;j<8;j++)
#pragma unroll
        for (int e=0;e<4;e++) sacc[i][j][e]=0.f;

#pragma unroll
    for (int t=0;t<3;t++){
      const uint32_t qb_ = qb_t[t] + (uint32_t)(warpM*32*QB) + a_off;
      const uint32_t kb_ = kb_t[t] + (uint32_t)(warpN*64*QB) + b_off;
#pragma unroll
      for (int k16=0;k16<4;k16++){
        uint32_t af[2][4];
        ldsm4(af[0], qb_ + k16*32);
        ldsm4(af[1], qb_ + 16*QB + k16*32);
#pragma unroll
        for (int nf=0;nf<4;nf++){
          uint32_t bf[4];
          ldsm4(bf, kb_ + (uint32_t)(nf*16*QB) + k16*32);
          mma16816(sacc[0][2*nf],   af[0], bf);
          mma16816(sacc[0][2*nf+1], af[0], bf+2);
          mma16816(sacc[1][2*nf],   af[1], bf);
          mma16816(sacc[1][2*nf+1], af[1], bf+2);
        }
      }
    }

    // ---- scale*adj, exp, row sums, store P hi/lo ----
#pragma unroll
    for (int mi=0;mi<2;mi++){
      const int rr = r0 + mi*16;
      float rs0 = 0.f, rs8 = 0.f;
#pragma unroll
      for (int nf=0;nf<8;nf++){
        const int cc = cb + nf*8;
        float m0=1.f,m1=1.f,m2=1.f,m3=1.f;
        if (ua){
          const float* ar = adj + ((size_t)(rowg0+q0+rr))*512 + kb*128 + cc;
          float2 a01 = *reinterpret_cast<const float2*>(ar);
          float2 a23 = *reinterpret_cast<const float2*>(ar + 8*512);
          m0=a01.x; m1=a01.y; m2=a23.x; m3=a23.y;
        }
        float p0 = fexp(sacc[mi][nf][0]*0.125f*m0);
        float p1 = fexp(sacc[mi][nf][1]*0.125f*m1);
        float p2 = fexp(sacc[mi][nf][2]*0.125f*m2);
        float p3 = fexp(sacc[mi][nf][3]*0.125f*m3);
        rs0 += p0+p1;  rs8 += p2+p3;
        __nv_bfloat16 h0=__float2bfloat16(p0), h1=__float2bfloat16(p1);
        __nv_bfloat16 h2=__float2bfloat16(p2), h3=__float2bfloat16(p3);
        uint32_t ph01, ph23, pl01, pl23;
        {
          __nv_bfloat162 t0 = __halves2bfloat162(h0,h1);
          __nv_bfloat162 t1 = __halves2bfloat162(h2,h3);
          __nv_bfloat162 t2 = __halves2bfloat162(__float2bfloat16(p0-__bfloat162float(h0)),
                                                 __float2bfloat16(p1-__bfloat162float(h1)));
          __nv_bfloat162 t3 = __halves2bfloat162(__float2bfloat16(p2-__bfloat162float(h2)),
                                                 __float2bfloat16(p3-__bfloat162float(h3)));
          ph01 = *reinterpret_cast<uint32_t*>(&t0);
          ph23 = *reinterpret_cast<uint32_t*>(&t1);
          pl01 = *reinterpret_cast<uint32_t*>(&t2);
          pl23 = *reinterpret_cast<uint32_t*>(&t3);
        }
        uint32_t pa = sb + OPH + (uint32_t)(rr*PB + cc*2);
        uint32_t pb_ = sb + OPL + (uint32_t)(rr*PB + cc*2);
        asm volatile("st.shared.b32 [%0], %1;" :: "r"(pa), "r"(ph01));
        asm volatile("st.shared.b32 [%0], %1;" :: "r"(pa + 8*PB), "r"(ph23));
        asm volatile("st.shared.b32 [%0], %1;" :: "r"(pb_), "r"(pl01));
        asm volatile("st.shared.b32 [%0], %1;" :: "r"(pb_ + 8*PB), "r"(pl23));
      }
      rs0 += __shfl_xor_sync(0xffffffffu, rs0, 1);
      rs0 += __shfl_xor_sync(0xffffffffu, rs0, 2);
      rs8 += __shfl_xor_sync(0xffffffffu, rs8, 1);
      rs8 += __shfl_xor_sync(0xffffffffu, rs8, 2);
      if ((lane&3)==0){
        lp[warpN*128 + rr]     += rs0;
        lp[warpN*128 + rr + 8] += rs8;
      }
    }
    __syncthreads();

    if (kb < 3){
      at_load_tile(sb+OKH, kh, krow0+128, col0, tid);
      at_load_tile(sb+OKL, kl, krow0+128, col0, tid);
      asm volatile("cp.async.commit_group;" ::: "memory");
    }

    // ---- O += P V (3 terms), V^T via ldmatrix.trans ----
#pragma unroll
    for (int t=0;t<3;t++){
      const uint32_t pb2 = pb_t[t] + (uint32_t)(warpM*32*PB) + ap_off;
      const uint32_t vb2 = vb_t[t] + (uint32_t)((lane&15)*QB + (warpN*32 + (lane>>4)*8)*2);
#pragma unroll
      for (int k16=0;k16<8;k16++){
        uint32_t af[2][4];
        ldsm4(af[0], pb2 + k16*32);
        ldsm4(af[1], pb2 + 16*PB + k16*32);
#pragma unroll
        for (int nf=0;nf<2;nf++){
          uint32_t bf[4];
          ldsm4t(bf, vb2 + (uint32_t)(k16*16*QB) + (uint32_t)(nf*16*2));
          mma16816(oacc[0][2*nf],   af[0], bf);
          mma16816(oacc[0][2*nf+1], af[0], bf+2);
          mma16816(oacc[1][2*nf],   af[1], bf);
          mma16816(oacc[1][2*nf+1], af[1], bf+2);
        }
      }
    }
    __syncthreads();

    if (kb < 3){
      at_load_tile(sb+OVH, vh, krow0+128, col0, tid);
      at_load_tile(sb+OVL, vl, krow0+128, col0, tid);
      asm volatile("cp.async.commit_group;" ::: "memory");
      asm volatile("cp.async.wait_group 0;" ::: "memory");
      __syncthreads();
    }
  }

  // ---- epilogue: normalize, split, store ----
  if (tid < 128) lp[tid] = 1.f / (lp[tid] + lp[128 + tid]);
  __syncthreads();
#pragma unroll
  for (int mi=0;mi<2;mi++){
    const int rr = r0 + mi*16;
    const float inv0 = lp[rr], inv8 = lp[rr+8];
    const size_t rga = (size_t)(rowg0 + q0 + rr);
#pragma unroll
    for (int nf=0;nf<4;nf++){
      const int colg = col0 + warpN*32 + nf*8 + 2*(lane&3);
      float c0 = oacc[mi][nf][0]*inv0, c1 = oacc[mi][nf][1]*inv0;
      float c2 = oacc[mi][nf][2]*inv8, c3 = oacc[mi][nf][3]*inv8;
      __nv_bfloat16 h0=__float2bfloat16(c0), h1=__float2bfloat16(c1);
      __nv_bfloat16 h2=__float2bfloat16(c2), h3=__float2bfloat16(c3);
      *reinterpret_cast<__nv_bfloat162*>(&ch[rga*512 + colg]) = __halves2bfloat162(h0,h1);
      *reinterpret_cast<__nv_bfloat162*>(&ch[(rga+8)*512 + colg]) = __halves2bfloat162(h2,h3);
      *reinterpret_cast<__nv_bfloat162*>(&cl[rga*512 + colg]) =
          __halves2bfloat162(__float2bfloat16(c0-__bfloat162float(h0)),
                             __float2bfloat16(c1-__bfloat162float(h1)));
      *reinterpret_cast<__nv_bfloat162*>(&cl[(rga+8)*512 + colg]) =
          __halves2bfloat162(__float2bfloat16(c2-__bfloat162float(h2)),
                             __float2bfloat16(c3-__bfloat162float(h3)));
    }
  }
}

// ---------------- Gate + blend: out = c*x + (1-c)*h2 -----------------------
__global__ void gate_kernel(const float* __restrict__ x, const float* __restrict__ h2,
    const float* __restrict__ gw, const float* __restrict__ gb, float* __restrict__ out)
{
  const int w = threadIdx.x>>5, lane = threadIdx.x&31;
  const int row = blockIdx.x*8 + w;
  const float* xr = x  + (size_t)row*512;
  const float* hr = h2 + (size_t)row*512;
  float s = 0.f;
#pragma unroll
  for (int i=0;i<16;i++){
    int c = i*32 + lane;
    s += xr[c]*gw[c] + hr[c]*gw[512+c];
  }
#pragma unroll
  for (int off=16;off;off>>=1) s += __shfl_xor_sync(0xffffffffu,s,off);
  s += gb[0];
  float coeff = 1.f/(1.f+__expf(-s));
  float* orow = out + (size_t)row*512;
#pragma unroll
  for (int i=0;i<16;i++){
    int c = i*32+lane;
    orow[c] = coeff*xr[c] + (1.f-coeff)*hr[c];
  }
}

// ---------------- launch ---------------------------------------------------
extern "C" void kernel_launch(void* const* d_in, const int* in_sizes, int n_in,
                              void* d_out, int out_size)
{
  const float* x   = (const float*)d_in[0];
  const float* adj = (const float*)d_in[1];
  const float* W_w = (const float*)d_in[2];
  const float* W_b = (const float*)d_in[3];
  const float* lng = (const float*)d_in[4];
  const float* lnb = (const float*)d_in[5];
  const float* Wq  = (const float*)d_in[6];
  const float* bq  = (const float*)d_in[7];
  const float* Wk  = (const float*)d_in[8];
  const float* bk  = (const float*)d_in[9];
  const float* Wv  = (const float*)d_in[10];
  const float* bv  = (const float*)d_in[11];
  const float* Wo  = (const float*)d_in[12];
  const float* bo  = (const float*)d_in[13];
  const float* gw  = (const float*)d_in[14];
  const float* gbb = (const float*)d_in[15];
  const int*   ua  = (const int*)d_in[16];
  float* out = (float*)d_out;

  float *h,*h2;
  cudaGetSymbolAddress((void**)&h,   g_h);
  cudaGetSymbolAddress((void**)&h2,  g_h2);

  __nv_bfloat16 *xh,*xl,*hh,*hl,*qh,*ql,*kh,*kl,*vh,*vl,*ch,*cl;
  __nv_bfloat16 *wwh,*wwl,*wqh,*wql,*wkh,*wkl,*wvh,*wvl,*woh,*wol;
  cudaGetSymbolAddress((void**)&xh, g_xh);  cudaGetSymbolAddress((void**)&xl, g_xl);
  cudaGetSymbolAddress((void**)&hh, g_hh);  cudaGetSymbolAddress((void**)&hl, g_hl);
  cudaGetSymbolAddress((void**)&qh, g_qh);  cudaGetSymbolAddress((void**)&ql, g_ql);
  cudaGetSymbolAddress((void**)&kh, g_kh);  cudaGetSymbolAddress((void**)&kl, g_kl);
  cudaGetSymbolAddress((void**)&vh, g_vh);  cudaGetSymbolAddress((void**)&vl, g_vl);
  cudaGetSymbolAddress((void**)&ch, g_ch);  cudaGetSymbolAddress((void**)&cl, g_cl);
  cudaGetSymbolAddress((void**)&wwh, g_wwh); cudaGetSymbolAddress((void**)&wwl, g_wwl);
  cudaGetSymbolAddress((void**)&wqh, g_wqh); cudaGetSymbolAddress((void**)&wql, g_wql);
  cudaGetSymbolAddress((void**)&wkh, g_wkh); cudaGetSymbolAddress((void**)&wkl, g_wkl);
  cudaGetSymbolAddress((void**)&wvh, g_wvh); cudaGetSymbolAddress((void**)&wvl, g_wvl);
  cudaGetSymbolAddress((void**)&woh, g_woh); cudaGetSymbolAddress((void**)&wol, g_wol);

  cudaFuncSetAttribute(gemm_mma, cudaFuncAttributeMaxDynamicSharedMemorySize, GEMM_SMEM);
  cudaFuncSetAttribute(gemm_qkv, cudaFuncAttributeMaxDynamicSharedMemorySize, GEMM_SMEM);
  cudaFuncSetAttribute(attn_mma, cudaFuncAttributeMaxDynamicSharedMemorySize, AT_SMEM);

  QKVArgs qa;
  qa.bh0=wqh; qa.bl0=wql; qa.bh1=wkh; qa.bl1=wkl; qa.bh2=wvh; qa.bl2=wvl;
  qa.bias0=bq; qa.bias1=bk; qa.bias2=bv;
  qa.ch0=qh; qa.cl0=ql; qa.ch1=kh; qa.cl1=kl; qa.ch2=vh; qa.cl2=vl;

  dim3 tsg(16,16), tsb(32,8);
  dim3 gg(4,64);

  tsplit<<<tsg,tsb>>>(W_w, wwh, wwl);
  split_hl<<<4096,256>>>(x, xh, xl);
  gemm_mma<<<gg,256,GEMM_SMEM>>>(xh,xl,wwh,wwl,W_b,h,0,0,0);
  ln_split<<<8192,256>>>(h, lng, lnb, hh, hl);
  tsplit<<<tsg,tsb>>>(Wq, wqh, wql);
  tsplit<<<tsg,tsb>>>(Wk, wkh, wkl);
  tsplit<<<tsg,tsb>>>(Wv, wvh, wvl);
  gemm_qkv<<<dim3(12,64),256,GEMM_SMEM>>>(hh, hl, qa);
  tsplit<<<tsg,tsb>>>(Wo, woh, wol);
  attn_mma<<<dim3(4,8,16),256,AT_SMEM>>>(qh,ql,kh,kl,vh,vl,adj,ua,ch,cl);
  gemm_mma<<<gg,256,GEMM_SMEM>>>(ch,cl,woh,wol,bo,h2,0,0,1);
  gate_kernel<<<1024,256>>>(x, h2, gw, gbb, out);
}

// round 9
// speedup vs baseline: 1.7881x; 1.1922x over previous
#include <cuda_runtime.h>
#include <cuda_bf16.h>
#include <cstdint>

// Problem constants
#define MB 16
#define NT 512
#define DM 512
#define MROWS (MB*NT)   // 8192

// ---------------- scratch (static device arrays; no cudaMalloc allowed) ----
static __device__ float g_h  [MROWS*DM];
static __device__ float g_h2 [MROWS*DM];

// bf16 hi/lo splits
static __device__ __nv_bfloat16 g_xh[MROWS*DM], g_xl[MROWS*DM];
static __device__ __nv_bfloat16 g_hh[MROWS*DM], g_hl[MROWS*DM];
static __device__ __nv_bfloat16 g_qh[MROWS*DM], g_ql[MROWS*DM];
static __device__ __nv_bfloat16 g_kh[MROWS*DM], g_kl[MROWS*DM];
static __device__ __nv_bfloat16 g_vh[MROWS*DM], g_vl[MROWS*DM];
static __device__ __nv_bfloat16 g_ch[MROWS*DM], g_cl[MROWS*DM];
// bf16 hi/lo of transposed weights ([n,k] so D = A·B^T = A·W)
static __device__ __nv_bfloat16 g_wwh[DM*DM], g_wwl[DM*DM];
static __device__ __nv_bfloat16 g_wqh[DM*DM], g_wql[DM*DM];
static __device__ __nv_bfloat16 g_wkh[DM*DM], g_wkl[DM*DM];
static __device__ __nv_bfloat16 g_wvh[DM*DM], g_wvl[DM*DM];
static __device__ __nv_bfloat16 g_woh[DM*DM], g_wol[DM*DM];

__device__ __forceinline__ uint32_t s2u(const void* p){
  return (uint32_t)__cvta_generic_to_shared(p);
}

// ---------------- mma.sync helpers -----------------------------------------
__device__ __forceinline__ void ldsm4(uint32_t* r, uint32_t addr){
  asm volatile("ldmatrix.sync.aligned.m8n8.x4.shared.b16 {%0,%1,%2,%3}, [%4];"
   : "=r"(r[0]),"=r"(r[1]),"=r"(r[2]),"=r"(r[3]) : "r"(addr));
}
__device__ __forceinline__ void ldsm4t(uint32_t* r, uint32_t addr){
  asm volatile("ldmatrix.sync.aligned.m8n8.x4.trans.shared.b16 {%0,%1,%2,%3}, [%4];"
   : "=r"(r[0]),"=r"(r[1]),"=r"(r[2]),"=r"(r[3]) : "r"(addr));
}
__device__ __forceinline__ void mma16816(float* d, const uint32_t* a, const uint32_t* b){
  asm volatile("mma.sync.aligned.m16n8k16.row.col.f32.bf16.bf16.f32 "
    "{%0,%1,%2,%3}, {%4,%5,%6,%7}, {%8,%9}, {%0,%1,%2,%3};"
    : "+f"(d[0]),"+f"(d[1]),"+f"(d[2]),"+f"(d[3])
    : "r"(a[0]),"r"(a[1]),"r"(a[2]),"r"(a[3]), "r"(b[0]),"r"(b[1]));
}

// fast exp: fp32 accuracy ~2.4e-6, runs on fma/alu pipes (no MUFU)
__device__ __forceinline__ float fexp(float x){
  float y = x * 1.44269504f;
  int   ki = __float2int_rn(y);
  float f  = y - (float)ki;
  float p = 1.333355815e-3f;
  p = fmaf(p, f, 9.618129107e-3f);
  p = fmaf(p, f, 5.550410866e-2f);
  p = fmaf(p, f, 2.402265069e-1f);
  p = fmaf(p, f, 6.931471806e-1f);
  p = fmaf(p, f, 1.0f);
  return p * __int_as_float((ki + 127) << 23);
}

// ---------------- GEMM core: CTA tile 256x128, warp tile 64x64 --------------
// C[8192,512] = A @ W^T(+bias). 3 split terms, BK=64, 8 warps (4x2), 3-stage.
#define SA 72
#define A2BYTES (256*SA*2)           // 36864
#define B2BYTES (128*SA*2)           // 18432
#define STG2 (A2BYTES + B2BYTES)     // 55296
#define NSTG 3
#define GEMM_SMEM (NSTG*STG2)        // 165888
#define NC 24

struct GemmCore {
  uint32_t sbase;
  int m0, n0, tid, lane, warpM, warpN;
  float acc[4][8][4];

  __device__ __forceinline__ void init(uint32_t sb, int m0_, int n0_){
    sbase = sb; m0 = m0_; n0 = n0_;
    tid = threadIdx.x; lane = tid & 31;
    int wid = tid >> 5; warpM = wid >> 1; warpN = wid & 1;
#pragma unroll
    for (int i=0;i<4;i++)
#pragma unroll
      for (int j=0;j<8;j++)
#pragma unroll
        for (int r=0;r<4;r++) acc[i][j][r]=0.f;
  }

  __device__ __forceinline__ void load_chunk(int s, int c,
      const __nv_bfloat16* Ah, const __nv_bfloat16* Al,
      const __nv_bfloat16* Bh, const __nv_bfloat16* Bl){
    const __nv_bfloat16* Asrc = (c >= 16) ? Al : Ah;
    const __nv_bfloat16* Wsrc = (c >= 8 && c < 16) ? Bl : Bh;
    const int kk0 = (c & 7) * 64;
    const uint32_t da = sbase + s*STG2;
    const uint32_t db = da + A2BYTES;
    // A: 256 rows x 64 halves = 2048 16B units, 8 per thread
#pragma unroll
    for (int i=0;i<8;i++){
      int u = tid + i*256;
      int row = u >> 3, cc = u & 7;
      asm volatile("cp.async.cg.shared.global [%0], [%1], 16;"
        :: "r"(da + (uint32_t)(row*144 + cc*16)),
           "l"(Asrc + (size_t)(m0+row)*512 + kk0 + cc*8));
    }
    // B: 128 rows x 64 halves = 1024 units, 4 per thread
#pragma unroll
    for (int i=0;i<4;i++){
      int u = tid + i*256;
      int row = u >> 3, cc = u & 7;
      asm volatile("cp.async.cg.shared.global [%0], [%1], 16;"
        :: "r"(db + (uint32_t)(row*144 + cc*16)),
           "l"(Wsrc + (size_t)(n0+row)*512 + kk0 + cc*8));
    }
    asm volatile("cp.async.commit_group;" ::: "memory");
  }

  __device__ __forceinline__ void compute(int s){
    const uint32_t abase = sbase + s*STG2
        + (uint32_t)((warpM*64 + (lane & 15))*SA*2 + (lane >> 4)*16);
    const uint32_t bbase = sbase + s*STG2 + A2BYTES;
    const int n_off = ((lane >> 4) & 1) * 8 + (lane & 7);
    const int k_off = ((lane >> 3) & 1) * 8;
    uint32_t boff[4];
#pragma unroll
    for (int nip=0; nip<4; nip++)
      boff[nip] = bbase + (uint32_t)(((warpN*64 + nip*16 + n_off)*SA + k_off)*2);
#pragma unroll
    for (int k16=0; k16<4; k16++){
      uint32_t af[4][4];
#pragma unroll
      for (int mf=0; mf<4; mf++)
        ldsm4(af[mf], abase + (uint32_t)(mf*16*SA*2) + k16*32);
      uint32_t bfall[4][4];
#pragma unroll
      for (int nip=0; nip<4; nip++)
        ldsm4(bfall[nip], boff[nip] + k16*32);
#pragma unroll
      for (int mf=0; mf<4; mf++)
#pragma unroll
        for (int nip=0; nip<4; nip++){
          mma16816(acc[mf][2*nip],   af[mf], bfall[nip]);
          mma16816(acc[mf][2*nip+1], af[mf], bfall[nip]+2);
        }
    }
  }

  __device__ __forceinline__ void run(
      const __nv_bfloat16* Ah, const __nv_bfloat16* Al,
      const __nv_bfloat16* Bh, const __nv_bfloat16* Bl){
    load_chunk(0, 0, Ah, Al, Bh, Bl);
    load_chunk(1, 1, Ah, Al, Bh, Bl);
    for (int c=0; c<NC; c++){
      if (c < NC-1) asm volatile("cp.async.wait_group 1;" ::: "memory");
      else          asm volatile("cp.async.wait_group 0;" ::: "memory");
      __syncthreads();
      if (c+2 < NC) load_chunk((c+2)%NSTG, c+2, Ah, Al, Bh, Bl);
      compute(c%NSTG);
    }
  }

  // mode: 0 fp32, 1 fp32+relu, 2 bf16 hi/lo
  __device__ __forceinline__ void epilogue(const float* bias, float* C,
      __nv_bfloat16* Ch, __nv_bfloat16* Cl, int mode){
    const int g  = lane >> 2;
    const int tg = lane & 3;
#pragma unroll
    for (int mf=0; mf<4; mf++){
      const int row = m0 + warpM*64 + mf*16 + g;
#pragma unroll
      for (int ni=0; ni<8; ni++){
        const int col = n0 + warpN*64 + ni*8 + tg*2;
        const float b0 = bias[col], b1 = bias[col+1];
        float v[4] = {acc[mf][ni][0]+b0, acc[mf][ni][1]+b1,
                      acc[mf][ni][2]+b0, acc[mf][ni][3]+b1};
        if (mode == 1){
#pragma unroll
          for (int e=0;e<4;e++) v[e] = fmaxf(v[e],0.f);
        }
        if (mode == 2){
          __nv_bfloat16 h0=__float2bfloat16(v[0]), h1=__float2bfloat16(v[1]);
          __nv_bfloat16 h2=__float2bfloat16(v[2]), h3=__float2bfloat16(v[3]);
          *reinterpret_cast<__nv_bfloat162*>(&Ch[(size_t)row*512+col]) =
              __halves2bfloat162(h0,h1);
          *reinterpret_cast<__nv_bfloat162*>(&Ch[(size_t)(row+8)*512+col]) =
              __halves2bfloat162(h2,h3);
          *reinterpret_cast<__nv_bfloat162*>(&Cl[(size_t)row*512+col]) =
              __halves2bfloat162(__float2bfloat16(v[0]-__bfloat162float(h0)),
                                 __float2bfloat16(v[1]-__bfloat162float(h1)));
          *reinterpret_cast<__nv_bfloat162*>(&Cl[(size_t)(row+8)*512+col]) =
              __halves2bfloat162(__float2bfloat16(v[2]-__bfloat162float(h2)),
                                 __float2bfloat16(v[3]-__bfloat162float(h3)));
        } else {
          *reinterpret_cast<float2*>(&C[(size_t)row*512 + col])     = make_float2(v[0],v[1]);
          *reinterpret_cast<float2*>(&C[(size_t)(row+8)*512 + col]) = make_float2(v[2],v[3]);
        }
      }
    }
  }
};

__global__ __launch_bounds__(256,1) void gemm_mma(
    const __nv_bfloat16* __restrict__ Ah, const __nv_bfloat16* __restrict__ Al,
    const __nv_bfloat16* __restrict__ Bh, const __nv_bfloat16* __restrict__ Bl,
    const float* __restrict__ bias, float* __restrict__ C,
    __nv_bfloat16* __restrict__ Ch, __nv_bfloat16* __restrict__ Cl, int mode)
{
  extern __shared__ __align__(16) char smem_raw[];
  GemmCore core;
  core.init(s2u(smem_raw), blockIdx.y*256, blockIdx.x*128);
  core.run(Ah, Al, Bh, Bl);
  core.epilogue(bias, C, Ch, Cl, mode);
}

// Fused QKV: grid (12, 32); weight = blockIdx.x>>2, n-tile = blockIdx.x&3.
struct QKVArgs {
  const __nv_bfloat16 *bh0,*bl0,*bh1,*bl1,*bh2,*bl2;
  const float *bias0,*bias1,*bias2;
  __nv_bfloat16 *ch0,*cl0,*ch1,*cl1,*ch2,*cl2;
};

__global__ __launch_bounds__(256,1) void gemm_qkv(
    const __nv_bfloat16* __restrict__ Ah, const __nv_bfloat16* __restrict__ Al,
    QKVArgs a)
{
  extern __shared__ __align__(16) char smem_raw[];
  const int w = blockIdx.x >> 2;
  const __nv_bfloat16* Bh = (w==0) ? a.bh0 : (w==1) ? a.bh1 : a.bh2;
  const __nv_bfloat16* Bl = (w==0) ? a.bl0 : (w==1) ? a.bl1 : a.bl2;
  const float* bias       = (w==0) ? a.bias0 : (w==1) ? a.bias1 : a.bias2;
  __nv_bfloat16* Ch       = (w==0) ? a.ch0 : (w==1) ? a.ch1 : a.ch2;
  __nv_bfloat16* Cl       = (w==0) ? a.cl0 : (w==1) ? a.cl1 : a.cl2;
  GemmCore core;
  core.init(s2u(smem_raw), blockIdx.y*256, (blockIdx.x & 3)*128);
  core.run(Ah, Al, Bh, Bl);
  core.epilogue(bias, 0, Ch, Cl, 2);
}

// ---------------- fp32 -> bf16 hi/lo split ---------------------------------
__global__ void split_hl(const float* __restrict__ in,
                         __nv_bfloat16* __restrict__ hi,
                         __nv_bfloat16* __restrict__ lo)
{
  int i = blockIdx.x*256 + threadIdx.x;
  float4 v = reinterpret_cast<const float4*>(in)[i];
  float f[4] = {v.x, v.y, v.z, v.w};
  __nv_bfloat16 h[4], l[4];
#pragma unroll
  for (int j=0;j<4;j++){
    h[j] = __float2bfloat16(f[j]);
    l[j] = __float2bfloat16(f[j] - __bfloat162float(h[j]));
  }
  reinterpret_cast<__nv_bfloat162*>(hi)[2*i]   = __halves2bfloat162(h[0], h[1]);
  reinterpret_cast<__nv_bfloat162*>(hi)[2*i+1] = __halves2bfloat162(h[2], h[3]);
  reinterpret_cast<__nv_bfloat162*>(lo)[2*i]   = __halves2bfloat162(l[0], l[1]);
  reinterpret_cast<__nv_bfloat162*>(lo)[2*i+1] = __halves2bfloat162(l[2], l[3]);
}

// ---------------- all 5 weights: transposed bf16 hi/lo, one launch ---------
struct TsArgs {
  const float* w[5];
  __nv_bfloat16* th[5];
  __nv_bfloat16* tl[5];
};

__global__ void tsplit5(TsArgs a)
{
  __shared__ float t[32][33];
  const float* W        = a.w[blockIdx.z];
  __nv_bfloat16* Th     = a.th[blockIdx.z];
  __nv_bfloat16* Tl     = a.tl[blockIdx.z];
  const int bx = blockIdx.x*32;
  const int by = blockIdx.y*32;
  const int txx = threadIdx.x, tyy = threadIdx.y;
#pragma unroll
  for (int i=tyy;i<32;i+=8)
    t[i][txx] = W[(size_t)(by+i)*512 + bx + txx];
  __syncthreads();
#pragma unroll
  for (int i=tyy;i<32;i+=8){
    float v = t[txx][i];
    __nv_bfloat16 h = __float2bfloat16(v);
    __nv_bfloat16 l = __float2bfloat16(v - __bfloat162float(h));
    Th[(size_t)(bx+i)*512 + by + txx] = h;
    Tl[(size_t)(bx+i)*512 + by + txx] = l;
  }
}

// ---------------- LayerNorm + bf16 split -----------------------------------
__global__ void ln_split(const float* __restrict__ h, const float* __restrict__ g,
                         const float* __restrict__ b,
                         __nv_bfloat16* __restrict__ hh, __nv_bfloat16* __restrict__ hl)
{
  const int row = blockIdx.x;
  const int tid = threadIdx.x;
  const float* hr = h + (size_t)row*512;
  float v0 = hr[tid], v1 = hr[tid+256];
  __shared__ float red[8], red2[8];
  float s = v0+v1;
#pragma unroll
  for (int o=16;o;o>>=1) s += __shfl_xor_sync(0xffffffffu,s,o);
  if ((tid&31)==0) red[tid>>5]=s;
  __syncthreads();
  float mu = (red[0]+red[1]+red[2]+red[3]+red[4]+red[5]+red[6]+red[7]) * (1.f/512.f);
  float d0 = v0-mu, d1 = v1-mu;
  float q = d0*d0 + d1*d1;
#pragma unroll
  for (int o=16;o;o>>=1) q += __shfl_xor_sync(0xffffffffu,q,o);
  if ((tid&31)==0) red2[tid>>5]=q;
  __syncthreads();
  float var = (red2[0]+red2[1]+red2[2]+red2[3]+red2[4]+red2[5]+red2[6]+red2[7]) * (1.f/512.f);
  float rstd = rsqrtf(var + 1e-5f);
  float o0 = d0*rstd*g[tid]     + b[tid];
  float o1 = d1*rstd*g[tid+256] + b[tid+256];
  __nv_bfloat16 h0 = __float2bfloat16(o0);
  __nv_bfloat16 h1 = __float2bfloat16(o1);
  hh[(size_t)row*512 + tid]     = h0;
  hh[(size_t)row*512 + tid+256] = h1;
  hl[(size_t)row*512 + tid]     = __float2bfloat16(o0 - __bfloat162float(h0));
  hl[(size_t)row*512 + tid+256] = __float2bfloat16(o1 - __bfloat162float(h1));
}

// ---------------- Tensor-core flash attention (no-max softmax) -------------
#define QB 144
#define PB 272
#define OQH 0
#define OQL 18432
#define OKH 36864
#define OKL 55296
#define OVH 73728
#define OVL 92160
#define OPH 110592
#define OPL 145408
#define OLP 180224
#define AT_SMEM (OLP + 1024)

__device__ __forceinline__ void at_load_tile(uint32_t sdst,
    const __nv_bfloat16* __restrict__ g, int row0, int col0, int tid)
{
  int row = tid >> 1, half = tid & 1;
  uint32_t d = sdst + (uint32_t)(row*QB + half*64);
  const __nv_bfloat16* s = g + (size_t)(row0+row)*512 + col0 + half*32;
#pragma unroll
  for (int j=0;j<4;j++)
    asm volatile("cp.async.cg.shared.global [%0], [%1], 16;" :: "r"(d + j*16), "l"(s + j*8));
}

__global__ __launch_bounds__(256,1) void attn_mma(
    const __nv_bfloat16* __restrict__ qh, const __nv_bfloat16* __restrict__ ql,
    const __nv_bfloat16* __restrict__ kh, const __nv_bfloat16* __restrict__ kl,
    const __nv_bfloat16* __restrict__ vh, const __nv_bfloat16* __restrict__ vl,
    const float* __restrict__ adj, const int* __restrict__ use_adj,
    __nv_bfloat16* __restrict__ ch, __nv_bfloat16* __restrict__ cl)
{
  extern __shared__ __align__(16) char sm8[];
  const uint32_t sb = s2u(sm8);
  float* lp = reinterpret_cast<float*>(sm8 + OLP);

  const int tid = threadIdx.x, lane = tid & 31, wid = tid >> 5;
  const int warpM = wid >> 1, warpN = wid & 1;
  const int q0 = blockIdx.x * 128;
  const int hh = blockIdx.y, bb = blockIdx.z;
  const int ua = use_adj[0];
  const int col0 = hh * 64;
  const int rowg0 = bb * 512;

  at_load_tile(sb+OQH, qh, rowg0+q0, col0, tid);
  at_load_tile(sb+OQL, ql, rowg0+q0, col0, tid);
  lp[tid] = 0.f;

  float oacc[2][4][4];
#pragma unroll
  for (int i=0;i<2;i++)
#pragma unroll
    for (int j=0;j<4;j++)
#pragma unroll
      for (int e=0;e<4;e++) oacc[i][j][e]=0.f;

  const uint32_t a_off  = (uint32_t)((lane&15)*QB + (lane>>4)*16);
  const uint32_t b_off  = (uint32_t)((((lane>>4)&1)*8 + (lane&7))*QB + ((lane>>3)&1)*16);
  const uint32_t ap_off = (uint32_t)((lane&15)*PB + (lane>>4)*16);

  const uint32_t qb_t[3] = {sb+OQH, sb+OQH, sb+OQL};
  const uint32_t kb_t[3] = {sb+OKH, sb+OKL, sb+OKH};
  const uint32_t pb_t[3] = {sb+OPH, sb+OPH, sb+OPL};
  const uint32_t vb_t[3] = {sb+OVH, sb+OVL, sb+OVH};

  const int r0 = warpM*32 + (lane>>2);
  const int cb = warpN*64 + 2*(lane&3);

  for (int kb=0; kb<4; kb++){
    const int krow0 = rowg0 + kb*128;
    if (kb == 0){
      at_load_tile(sb+OKH, kh, krow0, col0, tid);
      at_load_tile(sb+OKL, kl, krow0, col0, tid);
      at_load_tile(sb+OVH, vh, krow0, col0, tid);
      at_load_tile(sb+OVL, vl, krow0, col0, tid);
      asm volatile("cp.async.commit_group;" ::: "memory");
      asm volatile("cp.async.wait_group 0;" ::: "memory");
      __syncthreads();
    }

    // ---- S = Q K^T (3 terms) ----
    float sacc[2][8][4];
#pragma unroll
    for (int i=0;i<2;i++)
#pragma unroll
      for (int j=0;j<8;j++)
#pragma unroll
        for (int e=0;e<4;e++) sacc[i][j][e]=0.f;

#pragma unroll
    for (int t=0;t<3;t++){
      const uint32_t qb_ = qb_t[t] + (uint32_t)(warpM*32*QB) + a_off;
      const uint32_t kb_ = kb_t[t] + (uint32_t)(warpN*64*QB) + b_off;
#pragma unroll
      for (int k16=0;k16<4;k16++){
        uint32_t af[2][4];
        ldsm4(af[0], qb_ + k16*32);
        ldsm4(af[1], qb_ + 16*QB + k16*32);
#pragma unroll
        for (int nf=0;nf<4;nf++){
          uint32_t bf[4];
          ldsm4(bf, kb_ + (uint32_t)(nf*16*QB) + k16*32);
          mma16816(sacc[0][2*nf],   af[0], bf);
          mma16816(sacc[0][2*nf+1], af[0], bf+2);
          mma16816(sacc[1][2*nf],   af[1], bf);
          mma16816(sacc[1][2*nf+1], af[1], bf+2);
        }
      }
    }

    // ---- scale*adj, exp, row sums, store P hi/lo ----
#pragma unroll
    for (int mi=0;mi<2;mi++){
      const int rr = r0 + mi*16;
      float rs0 = 0.f, rs8 = 0.f;
#pragma unroll
      for (int nf=0;nf<8;nf++){
        const int cc = cb + nf*8;
        float m0=1.f,m1=1.f,m2=1.f,m3=1.f;
        if (ua){
          const float* ar = adj + ((size_t)(rowg0+q0+rr))*512 + kb*128 + cc;
          float2 a01 = *reinterpret_cast<const float2*>(ar);
          float2 a23 = *reinterpret_cast<const float2*>(ar + 8*512);
          m0=a01.x; m1=a01.y; m2=a23.x; m3=a23.y;
        }
        float p0 = fexp(sacc[mi][nf][0]*0.125f*m0);
        float p1 = fexp(sacc[mi][nf][1]*0.125f*m1);
        float p2 = fexp(sacc[mi][nf][2]*0.125f*m2);
        float p3 = fexp(sacc[mi][nf][3]*0.125f*m3);
        rs0 += p0+p1;  rs8 += p2+p3;
        __nv_bfloat16 h0=__float2bfloat16(p0), h1=__float2bfloat16(p1);
        __nv_bfloat16 h2=__float2bfloat16(p2), h3=__float2bfloat16(p3);
        uint32_t ph01, ph23, pl01, pl23;
        {
          __nv_bfloat162 t0 = __halves2bfloat162(h0,h1);
          __nv_bfloat162 t1 = __halves2bfloat162(h2,h3);
          __nv_bfloat162 t2 = __halves2bfloat162(__float2bfloat16(p0-__bfloat162float(h0)),
                                                 __float2bfloat16(p1-__bfloat162float(h1)));
          __nv_bfloat162 t3 = __halves2bfloat162(__float2bfloat16(p2-__bfloat162float(h2)),
                                                 __float2bfloat16(p3-__bfloat162float(h3)));
          ph01 = *reinterpret_cast<uint32_t*>(&t0);
          ph23 = *reinterpret_cast<uint32_t*>(&t1);
          pl01 = *reinterpret_cast<uint32_t*>(&t2);
          pl23 = *reinterpret_cast<uint32_t*>(&t3);
        }
        uint32_t pa = sb + OPH + (uint32_t)(rr*PB + cc*2);
        uint32_t pb_ = sb + OPL + (uint32_t)(rr*PB + cc*2);
        asm volatile("st.shared.b32 [%0], %1;" :: "r"(pa), "r"(ph01));
        asm volatile("st.shared.b32 [%0], %1;" :: "r"(pa + 8*PB), "r"(ph23));
        asm volatile("st.shared.b32 [%0], %1;" :: "r"(pb_), "r"(pl01));
        asm volatile("st.shared.b32 [%0], %1;" :: "r"(pb_ + 8*PB), "r"(pl23));
      }
      rs0 += __shfl_xor_sync(0xffffffffu, rs0, 1);
      rs0 += __shfl_xor_sync(0xffffffffu, rs0, 2);
      rs8 += __shfl_xor_sync(0xffffffffu, rs8, 1);
      rs8 += __shfl_xor_sync(0xffffffffu, rs8, 2);
      if ((lane&3)==0){
        lp[warpN*128 + rr]     += rs0;
        lp[warpN*128 + rr + 8] += rs8;
      }
    }
    __syncthreads();

    if (kb < 3){
      at_load_tile(sb+OKH, kh, krow0+128, col0, tid);
      at_load_tile(sb+OKL, kl, krow0+128, col0, tid);
      asm volatile("cp.async.commit_group;" ::: "memory");
    }

    // ---- O += P V (3 terms), V^T via ldmatrix.trans ----
#pragma unroll
    for (int t=0;t<3;t++){
      const uint32_t pb2 = pb_t[t] + (uint32_t)(warpM*32*PB) + ap_off;
      const uint32_t vb2 = vb_t[t] + (uint32_t)((lane&15)*QB + (warpN*32 + (lane>>4)*8)*2);
#pragma unroll
      for (int k16=0;k16<8;k16++){
        uint32_t af[2][4];
        ldsm4(af[0], pb2 + k16*32);
        ldsm4(af[1], pb2 + 16*PB + k16*32);
#pragma unroll
        for (int nf=0;nf<2;nf++){
          uint32_t bf[4];
          ldsm4t(bf, vb2 + (uint32_t)(k16*16*QB) + (uint32_t)(nf*16*2));
          mma16816(oacc[0][2*nf],   af[0], bf);
          mma16816(oacc[0][2*nf+1], af[0], bf+2);
          mma16816(oacc[1][2*nf],   af[1], bf);
          mma16816(oacc[1][2*nf+1], af[1], bf+2);
        }
      }
    }
    __syncthreads();

    if (kb < 3){
      at_load_tile(sb+OVH, vh, krow0+128, col0, tid);
      at_load_tile(sb+OVL, vl, krow0+128, col0, tid);
      asm volatile("cp.async.commit_group;" ::: "memory");
      asm volatile("cp.async.wait_group 0;" ::: "memory");
      __syncthreads();
    }
  }

  // ---- epilogue: normalize, split, store ----
  if (tid < 128) lp[tid] = 1.f / (lp[tid] + lp[128 + tid]);
  __syncthreads();
#pragma unroll
  for (int mi=0;mi<2;mi++){
    const int rr = r0 + mi*16;
    const float inv0 = lp[rr], inv8 = lp[rr+8];
    const size_t rga = (size_t)(rowg0 + q0 + rr);
#pragma unroll
    for (int nf=0;nf<4;nf++){
      const int colg = col0 + warpN*32 + nf*8 + 2*(lane&3);
      float c0 = oacc[mi][nf][0]*inv0, c1 = oacc[mi][nf][1]*inv0;
      float c2 = oacc[mi][nf][2]*inv8, c3 = oacc[mi][nf][3]*inv8;
      __nv_bfloat16 h0=__float2bfloat16(c0), h1=__float2bfloat16(c1);
      __nv_bfloat16 h2=__float2bfloat16(c2), h3=__float2bfloat16(c3);
      *reinterpret_cast<__nv_bfloat162*>(&ch[rga*512 + colg]) = __halves2bfloat162(h0,h1);
      *reinterpret_cast<__nv_bfloat162*>(&ch[(rga+8)*512 + colg]) = __halves2bfloat162(h2,h3);
      *reinterpret_cast<__nv_bfloat162*>(&cl[rga*512 + colg]) =
          __halves2bfloat162(__float2bfloat16(c0-__bfloat162float(h0)),
                             __float2bfloat16(c1-__bfloat162float(h1)));
      *reinterpret_cast<__nv_bfloat162*>(&cl[(rga+8)*512 + colg]) =
          __halves2bfloat162(__float2bfloat16(c2-__bfloat162float(h2)),
                             __float2bfloat16(c3-__bfloat162float(h3)));
    }
  }
}

// ---------------- Gate + blend: out = c*x + (1-c)*h2 -----------------------
__global__ void gate_kernel(const float* __restrict__ x, const float* __restrict__ h2,
    const float* __restrict__ gw, const float* __restrict__ gb, float* __restrict__ out)
{
  const int w = threadIdx.x>>5, lane = threadIdx.x&31;
  const int row = blockIdx.x*8 + w;
  const float* xr = x  + (size_t)row*512;
  const float* hr = h2 + (size_t)row*512;
  float s = 0.f;
#pragma unroll
  for (int i=0;i<16;i++){
    int c = i*32 + lane;
    s += xr[c]*gw[c] + hr[c]*gw[512+c];
  }
#pragma unroll
  for (int off=16;off;off>>=1) s += __shfl_xor_sync(0xffffffffu,s,off);
  s += gb[0];
  float coeff = 1.f/(1.f+__expf(-s));
  float* orow = out + (size_t)row*512;
#pragma unroll
  for (int i=0;i<16;i++){
    int c = i*32+lane;
    orow[c] = coeff*xr[c] + (1.f-coeff)*hr[c];
  }
}

// ---------------- launch ---------------------------------------------------
extern "C" void kernel_launch(void* const* d_in, const int* in_sizes, int n_in,
                              void* d_out, int out_size)
{
  const float* x   = (const float*)d_in[0];
  const float* adj = (const float*)d_in[1];
  const float* W_w = (const float*)d_in[2];
  const float* W_b = (const float*)d_in[3];
  const float* lng = (const float*)d_in[4];
  const float* lnb = (const float*)d_in[5];
  const float* Wq  = (const float*)d_in[6];
  const float* bq  = (const float*)d_in[7];
  const float* Wk  = (const float*)d_in[8];
  const float* bk  = (const float*)d_in[9];
  const float* Wv  = (const float*)d_in[10];
  const float* bv  = (const float*)d_in[11];
  const float* Wo  = (const float*)d_in[12];
  const float* bo  = (const float*)d_in[13];
  const float* gw  = (const float*)d_in[14];
  const float* gbb = (const float*)d_in[15];
  const int*   ua  = (const int*)d_in[16];
  float* out = (float*)d_out;

  float *h,*h2;
  cudaGetSymbolAddress((void**)&h,   g_h);
  cudaGetSymbolAddress((void**)&h2,  g_h2);

  __nv_bfloat16 *xh,*xl,*hh,*hl,*qh,*ql,*kh,*kl,*vh,*vl,*ch,*cl;
  __nv_bfloat16 *wwh,*wwl,*wqh,*wql,*wkh,*wkl,*wvh,*wvl,*woh,*wol;
  cudaGetSymbolAddress((void**)&xh, g_xh);  cudaGetSymbolAddress((void**)&xl, g_xl);
  cudaGetSymbolAddress((void**)&hh, g_hh);  cudaGetSymbolAddress((void**)&hl, g_hl);
  cudaGetSymbolAddress((void**)&qh, g_qh);  cudaGetSymbolAddress((void**)&ql, g_ql);
  cudaGetSymbolAddress((void**)&kh, g_kh);  cudaGetSymbolAddress((void**)&kl, g_kl);
  cudaGetSymbolAddress((void**)&vh, g_vh);  cudaGetSymbolAddress((void**)&vl, g_vl);
  cudaGetSymbolAddress((void**)&ch, g_ch);  cudaGetSymbolAddress((void**)&cl, g_cl);
  cudaGetSymbolAddress((void**)&wwh, g_wwh); cudaGetSymbolAddress((void**)&wwl, g_wwl);
  cudaGetSymbolAddress((void**)&wqh, g_wqh); cudaGetSymbolAddress((void**)&wql, g_wql);
  cudaGetSymbolAddress((void**)&wkh, g_wkh); cudaGetSymbolAddress((void**)&wkl, g_wkl);
  cudaGetSymbolAddress((void**)&wvh, g_wvh); cudaGetSymbolAddress((void**)&wvl, g_wvl);
  cudaGetSymbolAddress((void**)&woh, g_woh); cudaGetSymbolAddress((void**)&wol, g_wol);

  cudaFuncSetAttribute(gemm_mma, cudaFuncAttributeMaxDynamicSharedMemorySize, GEMM_SMEM);
  cudaFuncSetAttribute(gemm_qkv, cudaFuncAttributeMaxDynamicSharedMemorySize, GEMM_SMEM);
  cudaFuncSetAttribute(attn_mma, cudaFuncAttributeMaxDynamicSharedMemorySize, AT_SMEM);

  QKVArgs qa;
  qa.bh0=wqh; qa.bl0=wql; qa.bh1=wkh; qa.bl1=wkl; qa.bh2=wvh; qa.bl2=wvl;
  qa.bias0=bq; qa.bias1=bk; qa.bias2=bv;
  qa.ch0=qh; qa.cl0=ql; qa.ch1=kh; qa.cl1=kl; qa.ch2=vh; qa.cl2=vl;

  TsArgs ts;
  ts.w[0]=W_w; ts.w[1]=Wq; ts.w[2]=Wk; ts.w[3]=Wv; ts.w[4]=Wo;
  ts.th[0]=wwh; ts.th[1]=wqh; ts.th[2]=wkh; ts.th[3]=wvh; ts.th[4]=woh;
  ts.tl[0]=wwl; ts.tl[1]=wql; ts.tl[2]=wkl; ts.tl[3]=wvl; ts.tl[4]=wol;

  tsplit5<<<dim3(16,16,5),dim3(32,8)>>>(ts);
  split_hl<<<4096,256>>>(x, xh, xl);
  gemm_mma<<<dim3(4,32),256,GEMM_SMEM>>>(xh,xl,wwh,wwl,W_b,h,0,0,0);
  ln_split<<<8192,256>>>(h, lng, lnb, hh, hl);
  gemm_qkv<<<dim3(12,32),256,GEMM_SMEM>>>(hh, hl, qa);
  attn_mma<<<dim3(4,8,16),256,AT_SMEM>>>(qh,ql,kh,kl,vh,vl,adj,ua,ch,cl);
  gemm_mma<<<dim3(4,32),256,GEMM_SMEM>>>(ch,cl,woh,wol,bo,h2,0,0,1);
  gate_kernel<<<1024,256>>>(x, h2, gw, gbb, out);
}

// round 10
// speedup vs baseline: 3.6548x; 2.0439x over previous
#include <cuda_runtime.h>
#include <cuda_fp16.h>
#include <cstdint>

// Problem constants
#define MROWS 8192
#define DM 512

// ---------------- scratch (static device arrays; no cudaMalloc allowed) ----
static __device__ float g_h  [MROWS*DM];
static __device__ float g_h2 [MROWS*DM];
static __device__ __half g_x16[MROWS*DM];
static __device__ __half g_h16[MROWS*DM];
static __device__ __half g_q16[MROWS*DM], g_k16[MROWS*DM], g_v16[MROWS*DM];
static __device__ __half g_c16[MROWS*DM];
// fp16 transposed weights ([n,k] so D = A·B^T = A·W)
static __device__ __half g_ww[DM*DM], g_wq[DM*DM], g_wk[DM*DM], g_wv[DM*DM], g_wo[DM*DM];

__device__ __forceinline__ uint32_t s2u(const void* p){
  return (uint32_t)__cvta_generic_to_shared(p);
}

// ---------------- mma.sync helpers -----------------------------------------
__device__ __forceinline__ void ldsm4(uint32_t* r, uint32_t addr){
  asm volatile("ldmatrix.sync.aligned.m8n8.x4.shared.b16 {%0,%1,%2,%3}, [%4];"
   : "=r"(r[0]),"=r"(r[1]),"=r"(r[2]),"=r"(r[3]) : "r"(addr));
}
__device__ __forceinline__ void ldsm4t(uint32_t* r, uint32_t addr){
  asm volatile("ldmatrix.sync.aligned.m8n8.x4.trans.shared.b16 {%0,%1,%2,%3}, [%4];"
   : "=r"(r[0]),"=r"(r[1]),"=r"(r[2]),"=r"(r[3]) : "r"(addr));
}
__device__ __forceinline__ void mma16816(float* d, const uint32_t* a, const uint32_t* b){
  asm volatile("mma.sync.aligned.m16n8k16.row.col.f32.f16.f16.f32 "
    "{%0,%1,%2,%3}, {%4,%5,%6,%7}, {%8,%9}, {%0,%1,%2,%3};"
    : "+f"(d[0]),"+f"(d[1]),"+f"(d[2]),"+f"(d[3])
    : "r"(a[0]),"r"(a[1]),"r"(a[2]),"r"(a[3]), "r"(b[0]),"r"(b[1]));
}

// fast exp: fp32 accuracy ~2.4e-6, runs on fma/alu pipes (no MUFU)
__device__ __forceinline__ float fexp(float x){
  float y = x * 1.44269504f;
  int   ki = __float2int_rn(y);
  float f  = y - (float)ki;
  float p = 1.333355815e-3f;
  p = fmaf(p, f, 9.618129107e-3f);
  p = fmaf(p, f, 5.550410866e-2f);
  p = fmaf(p, f, 2.402265069e-1f);
  p = fmaf(p, f, 6.931471806e-1f);
  p = fmaf(p, f, 1.0f);
  return p * __int_as_float((ki + 127) << 23);
}

// ---------------- GEMM core: CTA tile 256x128, warp tile 64x64, fp16 -------
// C[8192,512] = A @ W^T(+bias). Single fp16 term, BK=64, 8 warps (4x2), 3-stage.
#define SA 72
#define A2BYTES (256*SA*2)           // 36864
#define B2BYTES (128*SA*2)           // 18432
#define STG2 (A2BYTES + B2BYTES)     // 55296
#define NSTG 3
#define GEMM_SMEM (NSTG*STG2)        // 165888
#define NC 8

struct GemmCore {
  uint32_t sbase;
  int m0, n0, tid, lane, warpM, warpN;
  float acc[4][8][4];

  __device__ __forceinline__ void init(uint32_t sb, int m0_, int n0_){
    sbase = sb; m0 = m0_; n0 = n0_;
    tid = threadIdx.x; lane = tid & 31;
    int wid = tid >> 5; warpM = wid >> 1; warpN = wid & 1;
#pragma unroll
    for (int i=0;i<4;i++)
#pragma unroll
      for (int j=0;j<8;j++)
#pragma unroll
        for (int r=0;r<4;r++) acc[i][j][r]=0.f;
  }

  __device__ __forceinline__ void load_chunk(int s, int c,
      const __half* A, const __half* W){
    const int kk0 = c * 64;
    const uint32_t da = sbase + s*STG2;
    const uint32_t db = da + A2BYTES;
#pragma unroll
    for (int i=0;i<8;i++){
      int u = tid + i*256;
      int row = u >> 3, cc = u & 7;
      asm volatile("cp.async.cg.shared.global [%0], [%1], 16;"
        :: "r"(da + (uint32_t)(row*144 + cc*16)),
           "l"(A + (size_t)(m0+row)*512 + kk0 + cc*8));
    }
#pragma unroll
    for (int i=0;i<4;i++){
      int u = tid + i*256;
      int row = u >> 3, cc = u & 7;
      asm volatile("cp.async.cg.shared.global [%0], [%1], 16;"
        :: "r"(db + (uint32_t)(row*144 + cc*16)),
           "l"(W + (size_t)(n0+row)*512 + kk0 + cc*8));
    }
    asm volatile("cp.async.commit_group;" ::: "memory");
  }

  __device__ __forceinline__ void compute(int s){
    const uint32_t abase = sbase + s*STG2
        + (uint32_t)((warpM*64 + (lane & 15))*SA*2 + (lane >> 4)*16);
    const uint32_t bbase = sbase + s*STG2 + A2BYTES;
    const int n_off = ((lane >> 4) & 1) * 8 + (lane & 7);
    const int k_off = ((lane >> 3) & 1) * 8;
    uint32_t boff[4];
#pragma unroll
    for (int nip=0; nip<4; nip++)
      boff[nip] = bbase + (uint32_t)(((warpN*64 + nip*16 + n_off)*SA + k_off)*2);
#pragma unroll
    for (int k16=0; k16<4; k16++){
      uint32_t af[4][4];
#pragma unroll
      for (int mf=0; mf<4; mf++)
        ldsm4(af[mf], abase + (uint32_t)(mf*16*SA*2) + k16*32);
      uint32_t bfall[4][4];
#pragma unroll
      for (int nip=0; nip<4; nip++)
        ldsm4(bfall[nip], boff[nip] + k16*32);
#pragma unroll
      for (int mf=0; mf<4; mf++)
#pragma unroll
        for (int nip=0; nip<4; nip++){
          mma16816(acc[mf][2*nip],   af[mf], bfall[nip]);
          mma16816(acc[mf][2*nip+1], af[mf], bfall[nip]+2);
        }
    }
  }

  __device__ __forceinline__ void run(const __half* A, const __half* W){
    load_chunk(0, 0, A, W);
    load_chunk(1, 1, A, W);
    for (int c=0; c<NC; c++){
      if (c < NC-1) asm volatile("cp.async.wait_group 1;" ::: "memory");
      else          asm volatile("cp.async.wait_group 0;" ::: "memory");
      __syncthreads();
      if (c+2 < NC) load_chunk((c+2)%NSTG, c+2, A, W);
      compute(c%NSTG);
    }
  }

  // mode: 0 fp32, 1 fp32+relu, 2 fp16
  __device__ __forceinline__ void epilogue(const float* bias, float* C,
      __half* C16, int mode){
    const int g  = lane >> 2;
    const int tg = lane & 3;
#pragma unroll
    for (int mf=0; mf<4; mf++){
      const int row = m0 + warpM*64 + mf*16 + g;
#pragma unroll
      for (int ni=0; ni<8; ni++){
        const int col = n0 + warpN*64 + ni*8 + tg*2;
        const float b0 = bias[col], b1 = bias[col+1];
        float v[4] = {acc[mf][ni][0]+b0, acc[mf][ni][1]+b1,
                      acc[mf][ni][2]+b0, acc[mf][ni][3]+b1};
        if (mode == 1){
#pragma unroll
          for (int e=0;e<4;e++) v[e] = fmaxf(v[e],0.f);
        }
        if (mode == 2){
          *reinterpret_cast<__half2*>(&C16[(size_t)row*512+col]) =
              __halves2half2(__float2half(v[0]), __float2half(v[1]));
          *reinterpret_cast<__half2*>(&C16[(size_t)(row+8)*512+col]) =
              __halves2half2(__float2half(v[2]), __float2half(v[3]));
        } else {
          *reinterpret_cast<float2*>(&C[(size_t)row*512 + col])     = make_float2(v[0],v[1]);
          *reinterpret_cast<float2*>(&C[(size_t)(row+8)*512 + col]) = make_float2(v[2],v[3]);
        }
      }
    }
  }
};

__global__ __launch_bounds__(256,1) void gemm_mma(
    const __half* __restrict__ A, const __half* __restrict__ W,
    const float* __restrict__ bias, float* __restrict__ C,
    __half* __restrict__ C16, int mode)
{
  extern __shared__ __align__(16) char smem_raw[];
  GemmCore core;
  core.init(s2u(smem_raw), blockIdx.y*256, blockIdx.x*128);
  core.run(A, W);
  core.epilogue(bias, C, C16, mode);
}

// Fused QKV: grid (12, 32); weight = blockIdx.x>>2, n-tile = blockIdx.x&3.
struct QKVArgs {
  const __half *w0,*w1,*w2;
  const float *bias0,*bias1,*bias2;
  __half *c0,*c1,*c2;
};

__global__ __launch_bounds__(256,1) void gemm_qkv(
    const __half* __restrict__ A, QKVArgs a)
{
  extern __shared__ __align__(16) char smem_raw[];
  const int w = blockIdx.x >> 2;
  const __half* W    = (w==0) ? a.w0 : (w==1) ? a.w1 : a.w2;
  const float* bias  = (w==0) ? a.bias0 : (w==1) ? a.bias1 : a.bias2;
  __half* C16        = (w==0) ? a.c0 : (w==1) ? a.c1 : a.c2;
  GemmCore core;
  core.init(s2u(smem_raw), blockIdx.y*256, (blockIdx.x & 3)*128);
  core.run(A, W);
  core.epilogue(bias, 0, C16, 2);
}

// ---------------- fp32 -> fp16 convert -------------------------------------
__global__ void conv16(const float* __restrict__ in, __half* __restrict__ o)
{
  int i = blockIdx.x*256 + threadIdx.x;
  float4 v = reinterpret_cast<const float4*>(in)[i];
  reinterpret_cast<__half2*>(o)[2*i]   = __halves2half2(__float2half(v.x), __float2half(v.y));
  reinterpret_cast<__half2*>(o)[2*i+1] = __halves2half2(__float2half(v.z), __float2half(v.w));
}

// ---------------- all 5 weights: transposed fp16, one launch ---------------
struct TsArgs {
  const float* w[5];
  __half* t[5];
};

__global__ void tsplit5(TsArgs a)
{
  __shared__ float t[32][33];
  const float* W = a.w[blockIdx.z];
  __half* T      = a.t[blockIdx.z];
  const int bx = blockIdx.x*32;
  const int by = blockIdx.y*32;
  const int txx = threadIdx.x, tyy = threadIdx.y;
#pragma unroll
  for (int i=tyy;i<32;i+=8)
    t[i][txx] = W[(size_t)(by+i)*512 + bx + txx];
  __syncthreads();
#pragma unroll
  for (int i=tyy;i<32;i+=8)
    T[(size_t)(bx+i)*512 + by + txx] = __float2half(t[txx][i]);
}

// ---------------- LayerNorm -> fp16 ----------------------------------------
__global__ void ln_f16(const float* __restrict__ h, const float* __restrict__ g,
                       const float* __restrict__ b, __half* __restrict__ h16)
{
  const int row = blockIdx.x;
  const int tid = threadIdx.x;
  const float* hr = h + (size_t)row*512;
  float v0 = hr[tid], v1 = hr[tid+256];
  __shared__ float red[8], red2[8];
  float s = v0+v1;
#pragma unroll
  for (int o=16;o;o>>=1) s += __shfl_xor_sync(0xffffffffu,s,o);
  if ((tid&31)==0) red[tid>>5]=s;
  __syncthreads();
  float mu = (red[0]+red[1]+red[2]+red[3]+red[4]+red[5]+red[6]+red[7]) * (1.f/512.f);
  float d0 = v0-mu, d1 = v1-mu;
  float q = d0*d0 + d1*d1;
#pragma unroll
  for (int o=16;o;o>>=1) q += __shfl_xor_sync(0xffffffffu,q,o);
  if ((tid&31)==0) red2[tid>>5]=q;
  __syncthreads();
  float var = (red2[0]+red2[1]+red2[2]+red2[3]+red2[4]+red2[5]+red2[6]+red2[7]) * (1.f/512.f);
  float rstd = rsqrtf(var + 1e-5f);
  h16[(size_t)row*512 + tid]     = __float2half(d0*rstd*g[tid]     + b[tid]);
  h16[(size_t)row*512 + tid+256] = __float2half(d1*rstd*g[tid+256] + b[tid+256]);
}

// ---------------- Tensor-core flash attention (fp16, no-max softmax) -------
// Per CTA: (b, h, 128 q rows). 256 threads, 8 warps (4 warpM x 2 warpN).
#define QB 144
#define PB 272
#define OQ  0
#define OK0 18432
#define OK1 36864
#define OV  55296
#define OP  73728
#define OLP 108544
#define AT_SMEM (OLP + 1024)

__device__ __forceinline__ void at_load_tile(uint32_t sdst,
    const __half* __restrict__ g, int row0, int col0, int tid)
{
  int row = tid >> 1, half = tid & 1;
  uint32_t d = sdst + (uint32_t)(row*QB + half*64);
  const __half* s = g + (size_t)(row0+row)*512 + col0 + half*32;
#pragma unroll
  for (int j=0;j<4;j++)
    asm volatile("cp.async.cg.shared.global [%0], [%1], 16;" :: "r"(d + j*16), "l"(s + j*8));
}

__global__ __launch_bounds__(256,1) void attn_mma(
    const __half* __restrict__ q16, const __half* __restrict__ k16,
    const __half* __restrict__ v16,
    const float* __restrict__ adj, const int* __restrict__ use_adj,
    __half* __restrict__ c16)
{
  extern __shared__ __align__(16) char sm8[];
  const uint32_t sb = s2u(sm8);
  float* lp = reinterpret_cast<float*>(sm8 + OLP);

  const int tid = threadIdx.x, lane = tid & 31, wid = tid >> 5;
  const int warpM = wid >> 1, warpN = wid & 1;
  const int q0 = blockIdx.x * 128;
  const int hh = blockIdx.y, bb = blockIdx.z;
  const int ua = use_adj[0];
  const int col0 = hh * 64;
  const int rowg0 = bb * 512;

  at_load_tile(sb+OQ, q16, rowg0+q0, col0, tid);
  lp[tid] = 0.f;

  float oacc[2][4][4];
#pragma unroll
  for (int i=0;i<2;i++)
#pragma unroll
    for (int j=0;j<4;j++)
#pragma unroll
      for (int e=0;e<4;e++) oacc[i][j][e]=0.f;

  const uint32_t a_off  = (uint32_t)((lane&15)*QB + (lane>>4)*16);
  const uint32_t b_off  = (uint32_t)((((lane>>4)&1)*8 + (lane&7))*QB + ((lane>>3)&1)*16);
  const uint32_t ap_off = (uint32_t)((lane&15)*PB + (lane>>4)*16);

  const int r0 = warpM*32 + (lane>>2);
  const int cb = warpN*64 + 2*(lane&3);

  for (int kb=0; kb<4; kb++){
    const int krow0 = rowg0 + kb*128;
    if (kb == 0){
      at_load_tile(sb+OK0, k16, krow0, col0, tid);
      at_load_tile(sb+OV,  v16, krow0, col0, tid);
      asm volatile("cp.async.commit_group;" ::: "memory");
      asm volatile("cp.async.wait_group 0;" ::: "memory");
      __syncthreads();
    }

    // ---- S = Q K^T (single fp16 term) ----
    float sacc[2][8][4];
#pragma unroll
    for (int i=0;i<2;i++)
#pragma unroll
      for (int j=0;j<8;j++)
#pragma unroll
        for (int e=0;e<4;e++) sacc[i][j][e]=0.f;

    {
      const uint32_t qb_ = sb + OQ + (uint32_t)(warpM*32*QB) + a_off;
      const uint32_t kb_ = sb + ((kb&1) ? OK1 : OK0) + (uint32_t)(warpN*64*QB) + b_off;
#pragma unroll
      for (int k16i=0;k16i<4;k16i++){
        uint32_t af[2][4];
        ldsm4(af[0], qb_ + k16i*32);
        ldsm4(af[1], qb_ + 16*QB + k16i*32);
#pragma unroll
        for (int nf=0;nf<4;nf++){
          uint32_t bf[4];
          ldsm4(bf, kb_ + (uint32_t)(nf*16*QB) + k16i*32);
          mma16816(sacc[0][2*nf],   af[0], bf);
          mma16816(sacc[0][2*nf+1], af[0], bf+2);
          mma16816(sacc[1][2*nf],   af[1], bf);
          mma16816(sacc[1][2*nf+1], af[1], bf+2);
        }
      }
    }

    // ---- scale*adj, exp, row sums, store P fp16 ----
#pragma unroll
    for (int mi=0;mi<2;mi++){
      const int rr = r0 + mi*16;
      float rs0 = 0.f, rs8 = 0.f;
#pragma unroll
      for (int nf=0;nf<8;nf++){
        const int cc = cb + nf*8;
        float m0=1.f,m1=1.f,m2=1.f,m3=1.f;
        if (ua){
          const float* ar = adj + ((size_t)(rowg0+q0+rr))*512 + kb*128 + cc;
          float2 a01 = *reinterpret_cast<const float2*>(ar);
          float2 a23 = *reinterpret_cast<const float2*>(ar + 8*512);
          m0=a01.x; m1=a01.y; m2=a23.x; m3=a23.y;
        }
        float p0 = fexp(sacc[mi][nf][0]*0.125f*m0);
        float p1 = fexp(sacc[mi][nf][1]*0.125f*m1);
        float p2 = fexp(sacc[mi][nf][2]*0.125f*m2);
        float p3 = fexp(sacc[mi][nf][3]*0.125f*m3);
        rs0 += p0+p1;  rs8 += p2+p3;
        __half2 t0 = __halves2half2(__float2half(p0), __float2half(p1));
        __half2 t1 = __halves2half2(__float2half(p2), __float2half(p3));
        uint32_t ph01 = *reinterpret_cast<uint32_t*>(&t0);
        uint32_t ph23 = *reinterpret_cast<uint32_t*>(&t1);
        uint32_t pa = sb + OP + (uint32_t)(rr*PB + cc*2);
        asm volatile("st.shared.b32 [%0], %1;" :: "r"(pa), "r"(ph01));
        asm volatile("st.shared.b32 [%0], %1;" :: "r"(pa + 8*PB), "r"(ph23));
      }
      rs0 += __shfl_xor_sync(0xffffffffu, rs0, 1);
      rs0 += __shfl_xor_sync(0xffffffffu, rs0, 2);
      rs8 += __shfl_xor_sync(0xffffffffu, rs8, 1);
      rs8 += __shfl_xor_sync(0xffffffffu, rs8, 2);
      if ((lane&3)==0){
        lp[warpN*128 + rr]     += rs0;
        lp[warpN*128 + rr + 8] += rs8;
      }
    }
    __syncthreads();   // P visible; K[kb&1] free

    if (kb < 3){       // prefetch next K into other buffer while PV runs
      at_load_tile(sb + ((kb&1) ? OK0 : OK1), k16, krow0+128, col0, tid);
      asm volatile("cp.async.commit_group;" ::: "memory");
    }

    // ---- O += P V (single term), V^T via ldmatrix.trans ----
    {
      const uint32_t pb2 = sb + OP + (uint32_t)(warpM*32*PB) + ap_off;
      const uint32_t vb2 = sb + OV + (uint32_t)((lane&15)*QB + (warpN*32 + (lane>>4)*8)*2);
#pragma unroll
      for (int k16i=0;k16i<8;k16i++){
        uint32_t af[2][4];
        ldsm4(af[0], pb2 + k16i*32);
        ldsm4(af[1], pb2 + 16*PB + k16i*32);
#pragma unroll
        for (int nf=0;nf<2;nf++){
          uint32_t bf[4];
          ldsm4t(bf, vb2 + (uint32_t)(k16i*16*QB) + (uint32_t)(nf*16*2));
          mma16816(oacc[0][2*nf],   af[0], bf);
          mma16816(oacc[0][2*nf+1], af[0], bf+2);
          mma16816(oacc[1][2*nf],   af[1], bf);
          mma16816(oacc[1][2*nf+1], af[1], bf+2);
        }
      }
    }
    __syncthreads();   // V reads complete

    if (kb < 3){
      at_load_tile(sb+OV, v16, krow0+128, col0, tid);
      asm volatile("cp.async.commit_group;" ::: "memory");
      asm volatile("cp.async.wait_group 0;" ::: "memory");
      __syncthreads();
    }
  }

  // ---- epilogue: normalize, store fp16 ctx ----
  if (tid < 128) lp[tid] = 1.f / (lp[tid] + lp[128 + tid]);
  __syncthreads();
#pragma unroll
  for (int mi=0;mi<2;mi++){
    const int rr = r0 + mi*16;
    const float inv0 = lp[rr], inv8 = lp[rr+8];
    const size_t rga = (size_t)(rowg0 + q0 + rr);
#pragma unroll
    for (int nf=0;nf<4;nf++){
      const int colg = col0 + warpN*32 + nf*8 + 2*(lane&3);
      *reinterpret_cast<__half2*>(&c16[rga*512 + colg]) =
          __halves2half2(__float2half(oacc[mi][nf][0]*inv0),
                         __float2half(oacc[mi][nf][1]*inv0));
      *reinterpret_cast<__half2*>(&c16[(rga+8)*512 + colg]) =
          __halves2half2(__float2half(oacc[mi][nf][2]*inv8),
                         __float2half(oacc[mi][nf][3]*inv8));
    }
  }
}

// ---------------- Gate + blend: out = c*x + (1-c)*h2 -----------------------
__global__ void gate_kernel(const float* __restrict__ x, const float* __restrict__ h2,
    const float* __restrict__ gw, const float* __restrict__ gb, float* __restrict__ out)
{
  const int w = threadIdx.x>>5, lane = threadIdx.x&31;
  const int row = blockIdx.x*8 + w;
  const float* xr = x  + (size_t)row*512;
  const float* hr = h2 + (size_t)row*512;
  float s = 0.f;
#pragma unroll
  for (int i=0;i<16;i++){
    int c = i*32 + lane;
    s += xr[c]*gw[c] + hr[c]*gw[512+c];
  }
#pragma unroll
  for (int off=16;off;off>>=1) s += __shfl_xor_sync(0xffffffffu,s,off);
  s += gb[0];
  float coeff = 1.f/(1.f+__expf(-s));
  float* orow = out + (size_t)row*512;
#pragma unroll
  for (int i=0;i<16;i++){
    int c = i*32+lane;
    orow[c] = coeff*xr[c] + (1.f-coeff)*hr[c];
  }
}

// ---------------- launch ---------------------------------------------------
extern "C" void kernel_launch(void* const* d_in, const int* in_sizes, int n_in,
                              void* d_out, int out_size)
{
  const float* x   = (const float*)d_in[0];
  const float* adj = (const float*)d_in[1];
  const float* W_w = (const float*)d_in[2];
  const float* W_b = (const float*)d_in[3];
  const float* lng = (const float*)d_in[4];
  const float* lnb = (const float*)d_in[5];
  const float* Wq  = (const float*)d_in[6];
  const float* bq  = (const float*)d_in[7];
  const float* Wk  = (const float*)d_in[8];
  const float* bk  = (const float*)d_in[9];
  const float* Wv  = (const float*)d_in[10];
  const float* bv  = (const float*)d_in[11];
  const float* Wo  = (const float*)d_in[12];
  const float* bo  = (const float*)d_in[13];
  const float* gw  = (const float*)d_in[14];
  const float* gbb = (const float*)d_in[15];
  const int*   ua  = (const int*)d_in[16];
  float* out = (float*)d_out;

  float *h,*h2;
  cudaGetSymbolAddress((void**)&h,   g_h);
  cudaGetSymbolAddress((void**)&h2,  g_h2);

  __half *x16,*h16,*q16,*k16,*v16,*c16,*ww,*wq,*wk,*wv,*wo;
  cudaGetSymbolAddress((void**)&x16, g_x16);
  cudaGetSymbolAddress((void**)&h16, g_h16);
  cudaGetSymbolAddress((void**)&q16, g_q16);
  cudaGetSymbolAddress((void**)&k16, g_k16);
  cudaGetSymbolAddress((void**)&v16, g_v16);
  cudaGetSymbolAddress((void**)&c16, g_c16);
  cudaGetSymbolAddress((void**)&ww,  g_ww);
  cudaGetSymbolAddress((void**)&wq,  g_wq);
  cudaGetSymbolAddress((void**)&wk,  g_wk);
  cudaGetSymbolAddress((void**)&wv,  g_wv);
  cudaGetSymbolAddress((void**)&wo,  g_wo);

  cudaFuncSetAttribute(gemm_mma, cudaFuncAttributeMaxDynamicSharedMemorySize, GEMM_SMEM);
  cudaFuncSetAttribute(gemm_qkv, cudaFuncAttributeMaxDynamicSharedMemorySize, GEMM_SMEM);
  cudaFuncSetAttribute(attn_mma, cudaFuncAttributeMaxDynamicSharedMemorySize, AT_SMEM);

  QKVArgs qa;
  qa.w0=wq; qa.w1=wk; qa.w2=wv;
  qa.bias0=bq; qa.bias1=bk; qa.bias2=bv;
  qa.c0=q16; qa.c1=k16; qa.c2=v16;

  TsArgs ts;
  ts.w[0]=W_w; ts.w[1]=Wq; ts.w[2]=Wk; ts.w[3]=Wv; ts.w[4]=Wo;
  ts.t[0]=ww; ts.t[1]=wq; ts.t[2]=wk; ts.t[3]=wv; ts.t[4]=wo;

  tsplit5<<<dim3(16,16,5),dim3(32,8)>>>(ts);
  conv16<<<4096,256>>>(x, x16);
  gemm_mma<<<dim3(4,32),256,GEMM_SMEM>>>(x16, ww, W_b, h, 0, 0);
  ln_f16<<<8192,256>>>(h, lng, lnb, h16);
  gemm_qkv<<<dim3(12,32),256,GEMM_SMEM>>>(h16, qa);
  attn_mma<<<dim3(4,8,16),256,AT_SMEM>>>(q16,k16,v16,adj,ua,c16);
  gemm_mma<<<dim3(4,32),256,GEMM_SMEM>>>(c16, wo, bo, h2, 0, 1);
  gate_kernel<<<1024,256>>>(x, h2, gw, gbb, out);
}

// round 11
// speedup vs baseline: 3.7192x; 1.0176x over previous
#include <cuda_runtime.h>
#include <cuda_fp16.h>
#include <cstdint>

// Problem constants
#define MROWS 8192
#define DM 512

// ---------------- scratch (static device arrays; no cudaMalloc allowed) ----
static __device__ __half g_x16[MROWS*DM];
static __device__ __half g_hp16[MROWS*DM];   // pre-LN h (fp16)
static __device__ __half g_h16[MROWS*DM];    // post-LN h (fp16)
static __device__ __half g_q16[MROWS*DM], g_k16[MROWS*DM], g_v16[MROWS*DM];
static __device__ __half g_c16[MROWS*DM];    // attention ctx
static __device__ __half g_h2_16[MROWS*DM];  // relu(ctx@Wo+bo)
// fp16 transposed weights ([n,k] so D = A·B^T = A·W)
static __device__ __half g_ww[DM*DM], g_wq[DM*DM], g_wk[DM*DM], g_wv[DM*DM], g_wo[DM*DM];

__device__ __forceinline__ uint32_t s2u(const void* p){
  return (uint32_t)__cvta_generic_to_shared(p);
}

// ---------------- mma.sync helpers -----------------------------------------
__device__ __forceinline__ void ldsm4(uint32_t* r, uint32_t addr){
  asm volatile("ldmatrix.sync.aligned.m8n8.x4.shared.b16 {%0,%1,%2,%3}, [%4];"
   : "=r"(r[0]),"=r"(r[1]),"=r"(r[2]),"=r"(r[3]) : "r"(addr));
}
__device__ __forceinline__ void ldsm4t(uint32_t* r, uint32_t addr){
  asm volatile("ldmatrix.sync.aligned.m8n8.x4.trans.shared.b16 {%0,%1,%2,%3}, [%4];"
   : "=r"(r[0]),"=r"(r[1]),"=r"(r[2]),"=r"(r[3]) : "r"(addr));
}
__device__ __forceinline__ void mma16816(float* d, const uint32_t* a, const uint32_t* b){
  asm volatile("mma.sync.aligned.m16n8k16.row.col.f32.f16.f16.f32 "
    "{%0,%1,%2,%3}, {%4,%5,%6,%7}, {%8,%9}, {%0,%1,%2,%3};"
    : "+f"(d[0]),"+f"(d[1]),"+f"(d[2]),"+f"(d[3])
    : "r"(a[0]),"r"(a[1]),"r"(a[2]),"r"(a[3]), "r"(b[0]),"r"(b[1]));
}

// fast exp: fp32 accuracy ~2.4e-6, runs on fma/alu pipes (no MUFU)
__device__ __forceinline__ float fexp(float x){
  float y = x * 1.44269504f;
  int   ki = __float2int_rn(y);
  float f  = y - (float)ki;
  float p = 1.333355815e-3f;
  p = fmaf(p, f, 9.618129107e-3f);
  p = fmaf(p, f, 5.550410866e-2f);
  p = fmaf(p, f, 2.402265069e-1f);
  p = fmaf(p, f, 6.931471806e-1f);
  p = fmaf(p, f, 1.0f);
  return p * __int_as_float((ki + 127) << 23);
}

// ---------------- GEMM core: CTA tile 256x128, warp tile 64x64, fp16 -------
// C16[8192,512] = A @ W^T(+bias). BK=64, 8 warps (4x2), 3-stage cp.async ring.
#define SA 72
#define A2BYTES (256*SA*2)           // 36864
#define B2BYTES (128*SA*2)           // 18432
#define STG2 (A2BYTES + B2BYTES)     // 55296
#define NSTG 3
#define GEMM_SMEM (NSTG*STG2)        // 165888
#define NC 8

struct GemmCore {
  uint32_t sbase;
  int m0, n0, tid, lane, warpM, warpN;
  float acc[4][8][4];

  __device__ __forceinline__ void init(uint32_t sb, int m0_, int n0_){
    sbase = sb; m0 = m0_; n0 = n0_;
    tid = threadIdx.x; lane = tid & 31;
    int wid = tid >> 5; warpM = wid >> 1; warpN = wid & 1;
#pragma unroll
    for (int i=0;i<4;i++)
#pragma unroll
      for (int j=0;j<8;j++)
#pragma unroll
        for (int r=0;r<4;r++) acc[i][j][r]=0.f;
  }

  __device__ __forceinline__ void load_chunk(int s, int c,
      const __half* A, const __half* W){
    const int kk0 = c * 64;
    const uint32_t da = sbase + s*STG2;
    const uint32_t db = da + A2BYTES;
#pragma unroll
    for (int i=0;i<8;i++){
      int u = tid + i*256;
      int row = u >> 3, cc = u & 7;
      asm volatile("cp.async.cg.shared.global [%0], [%1], 16;"
        :: "r"(da + (uint32_t)(row*144 + cc*16)),
           "l"(A + (size_t)(m0+row)*512 + kk0 + cc*8));
    }
#pragma unroll
    for (int i=0;i<4;i++){
      int u = tid + i*256;
      int row = u >> 3, cc = u & 7;
      asm volatile("cp.async.cg.shared.global [%0], [%1], 16;"
        :: "r"(db + (uint32_t)(row*144 + cc*16)),
           "l"(W + (size_t)(n0+row)*512 + kk0 + cc*8));
    }
    asm volatile("cp.async.commit_group;" ::: "memory");
  }

  __device__ __forceinline__ void compute(int s){
    const uint32_t abase = sbase + s*STG2
        + (uint32_t)((warpM*64 + (lane & 15))*SA*2 + (lane >> 4)*16);
    const uint32_t bbase = sbase + s*STG2 + A2BYTES;
    const int n_off = ((lane >> 4) & 1) * 8 + (lane & 7);
    const int k_off = ((lane >> 3) & 1) * 8;
    uint32_t boff[4];
#pragma unroll
    for (int nip=0; nip<4; nip++)
      boff[nip] = bbase + (uint32_t)(((warpN*64 + nip*16 + n_off)*SA + k_off)*2);
#pragma unroll
    for (int k16=0; k16<4; k16++){
      uint32_t af[4][4];
#pragma unroll
      for (int mf=0; mf<4; mf++)
        ldsm4(af[mf], abase + (uint32_t)(mf*16*SA*2) + k16*32);
      uint32_t bfall[4][4];
#pragma unroll
      for (int nip=0; nip<4; nip++)
        ldsm4(bfall[nip], boff[nip] + k16*32);
#pragma unroll
      for (int mf=0; mf<4; mf++)
#pragma unroll
        for (int nip=0; nip<4; nip++){
          mma16816(acc[mf][2*nip],   af[mf], bfall[nip]);
          mma16816(acc[mf][2*nip+1], af[mf], bfall[nip]+2);
        }
    }
  }

  __device__ __forceinline__ void run(const __half* A, const __half* W){
    load_chunk(0, 0, A, W);
    load_chunk(1, 1, A, W);
    for (int c=0; c<NC; c++){
      if (c < NC-1) asm volatile("cp.async.wait_group 1;" ::: "memory");
      else          asm volatile("cp.async.wait_group 0;" ::: "memory");
      __syncthreads();
      if (c+2 < NC) load_chunk((c+2)%NSTG, c+2, A, W);
      compute(c%NSTG);
    }
  }

  // fp16 output; relu optional
  __device__ __forceinline__ void epilogue(const float* bias, __half* C16, int relu){
    const int g  = lane >> 2;
    const int tg = lane & 3;
#pragma unroll
    for (int mf=0; mf<4; mf++){
      const int row = m0 + warpM*64 + mf*16 + g;
#pragma unroll
      for (int ni=0; ni<8; ni++){
        const int col = n0 + warpN*64 + ni*8 + tg*2;
        const float b0 = bias[col], b1 = bias[col+1];
        float v[4] = {acc[mf][ni][0]+b0, acc[mf][ni][1]+b1,
                      acc[mf][ni][2]+b0, acc[mf][ni][3]+b1};
        if (relu){
#pragma unroll
          for (int e=0;e<4;e++) v[e] = fmaxf(v[e],0.f);
        }
        *reinterpret_cast<__half2*>(&C16[(size_t)row*512+col]) =
            __halves2half2(__float2half(v[0]), __float2half(v[1]));
        *reinterpret_cast<__half2*>(&C16[(size_t)(row+8)*512+col]) =
            __halves2half2(__float2half(v[2]), __float2half(v[3]));
      }
    }
  }
};

__global__ __launch_bounds__(256,1) void gemm_mma(
    const __half* __restrict__ A, const __half* __restrict__ W,
    const float* __restrict__ bias, __half* __restrict__ C16, int relu)
{
  extern __shared__ __align__(16) char smem_raw[];
  GemmCore core;
  core.init(s2u(smem_raw), blockIdx.y*256, blockIdx.x*128);
  core.run(A, W);
  core.epilogue(bias, C16, relu);
}

// Fused QKV: grid (12, 32); weight = blockIdx.x>>2, n-tile = blockIdx.x&3.
struct QKVArgs {
  const __half *w0,*w1,*w2;
  const float *bias0,*bias1,*bias2;
  __half *c0,*c1,*c2;
};

__global__ __launch_bounds__(256,1) void gemm_qkv(
    const __half* __restrict__ A, QKVArgs a)
{
  extern __shared__ __align__(16) char smem_raw[];
  const int w = blockIdx.x >> 2;
  const __half* W    = (w==0) ? a.w0 : (w==1) ? a.w1 : a.w2;
  const float* bias  = (w==0) ? a.bias0 : (w==1) ? a.bias1 : a.bias2;
  __half* C16        = (w==0) ? a.c0 : (w==1) ? a.c1 : a.c2;
  GemmCore core;
  core.init(s2u(smem_raw), blockIdx.y*256, (blockIdx.x & 3)*128);
  core.run(A, W);
  core.epilogue(bias, C16, 0);
}

// ---------------- fp32 -> fp16 convert -------------------------------------
__global__ void conv16(const float* __restrict__ in, __half* __restrict__ o)
{
  int i = blockIdx.x*256 + threadIdx.x;
  float4 v = reinterpret_cast<const float4*>(in)[i];
  reinterpret_cast<__half2*>(o)[2*i]   = __halves2half2(__float2half(v.x), __float2half(v.y));
  reinterpret_cast<__half2*>(o)[2*i+1] = __halves2half2(__float2half(v.z), __float2half(v.w));
}

// ---------------- all 5 weights: transposed fp16, one launch ---------------
struct TsArgs {
  const float* w[5];
  __half* t[5];
};

__global__ void tsplit5(TsArgs a)
{
  __shared__ float t[32][33];
  const float* W = a.w[blockIdx.z];
  __half* T      = a.t[blockIdx.z];
  const int bx = blockIdx.x*32;
  const int by = blockIdx.y*32;
  const int txx = threadIdx.x, tyy = threadIdx.y;
#pragma unroll
  for (int i=tyy;i<32;i+=8)
    t[i][txx] = W[(size_t)(by+i)*512 + bx + txx];
  __syncthreads();
#pragma unroll
  for (int i=tyy;i<32;i+=8)
    T[(size_t)(bx+i)*512 + by + txx] = __float2half(t[txx][i]);
}

// ---------------- LayerNorm (fp16 in -> fp16 out) --------------------------
__global__ void ln_f16(const __half* __restrict__ hp, const float* __restrict__ g,
                       const float* __restrict__ b, __half* __restrict__ h16)
{
  const int row = blockIdx.x;
  const int tid = threadIdx.x;
  const __half2* hr = reinterpret_cast<const __half2*>(hp + (size_t)row*512);
  __half2 hv = hr[tid];
  float v0 = __low2float(hv), v1 = __high2float(hv);
  __shared__ float red[8], red2[8];
  float s = v0+v1;
#pragma unroll
  for (int o=16;o;o>>=1) s += __shfl_xor_sync(0xffffffffu,s,o);
  if ((tid&31)==0) red[tid>>5]=s;
  __syncthreads();
  float mu = (red[0]+red[1]+red[2]+red[3]+red[4]+red[5]+red[6]+red[7]) * (1.f/512.f);
  float d0 = v0-mu, d1 = v1-mu;
  float q = d0*d0 + d1*d1;
#pragma unroll
  for (int o=16;o;o>>=1) q += __shfl_xor_sync(0xffffffffu,q,o);
  if ((tid&31)==0) red2[tid>>5]=q;
  __syncthreads();
  float var = (red2[0]+red2[1]+red2[2]+red2[3]+red2[4]+red2[5]+red2[6]+red2[7]) * (1.f/512.f);
  float rstd = rsqrtf(var + 1e-5f);
  float o0 = d0*rstd*g[2*tid]   + b[2*tid];
  float o1 = d1*rstd*g[2*tid+1] + b[2*tid+1];
  reinterpret_cast<__half2*>(h16 + (size_t)row*512)[tid] =
      __halves2half2(__float2half(o0), __float2half(o1));
}

// ---------------- Tensor-core flash attention (fp16, no-max softmax) -------
// Per CTA: (b, h, 128 q rows). 256 threads, 8 warps (4 warpM x 2 warpN).
#define QB 144
#define PB 272
#define OQ  0
#define OK0 18432
#define OK1 36864
#define OV  55296
#define OP  73728
#define OLP 108544
#define AT_SMEM (OLP + 1024)

__device__ __forceinline__ void at_load_tile(uint32_t sdst,
    const __half* __restrict__ g, int row0, int col0, int tid)
{
  int row = tid >> 1, half = tid & 1;
  uint32_t d = sdst + (uint32_t)(row*QB + half*64);
  const __half* s = g + (size_t)(row0+row)*512 + col0 + half*32;
#pragma unroll
  for (int j=0;j<4;j++)
    asm volatile("cp.async.cg.shared.global [%0], [%1], 16;" :: "r"(d + j*16), "l"(s + j*8));
}

__global__ __launch_bounds__(256,1) void attn_mma(
    const __half* __restrict__ q16, const __half* __restrict__ k16,
    const __half* __restrict__ v16,
    const float* __restrict__ adj, const int* __restrict__ use_adj,
    __half* __restrict__ c16)
{
  extern __shared__ __align__(16) char sm8[];
  const uint32_t sb = s2u(sm8);
  float* lp = reinterpret_cast<float*>(sm8 + OLP);

  const int tid = threadIdx.x, lane = tid & 31, wid = tid >> 5;
  const int warpM = wid >> 1, warpN = wid & 1;
  const int q0 = blockIdx.x * 128;
  const int hh = blockIdx.y, bb = blockIdx.z;
  const int ua = use_adj[0];
  const int col0 = hh * 64;
  const int rowg0 = bb * 512;

  at_load_tile(sb+OQ, q16, rowg0+q0, col0, tid);
  lp[tid] = 0.f;

  float oacc[2][4][4];
#pragma unroll
  for (int i=0;i<2;i++)
#pragma unroll
    for (int j=0;j<4;j++)
#pragma unroll
      for (int e=0;e<4;e++) oacc[i][j][e]=0.f;

  const uint32_t a_off  = (uint32_t)((lane&15)*QB + (lane>>4)*16);
  const uint32_t b_off  = (uint32_t)((((lane>>4)&1)*8 + (lane&7))*QB + ((lane>>3)&1)*16);
  const uint32_t ap_off = (uint32_t)((lane&15)*PB + (lane>>4)*16);

  const int r0 = warpM*32 + (lane>>2);
  const int cb = warpN*64 + 2*(lane&3);

  for (int kb=0; kb<4; kb++){
    const int krow0 = rowg0 + kb*128;
    if (kb == 0){
      at_load_tile(sb+OK0, k16, krow0, col0, tid);
      at_load_tile(sb+OV,  v16, krow0, col0, tid);
      asm volatile("cp.async.commit_group;" ::: "memory");
      asm volatile("cp.async.wait_group 0;" ::: "memory");
      __syncthreads();
    }

    // ---- S = Q K^T ----
    float sacc[2][8][4];
#pragma unroll
    for (int i=0;i<2;i++)
#pragma unroll
      for (int j=0;j<8;j++)
#pragma unroll
        for (int e=0;e<4;e++) sacc[i][j][e]=0.f;

    {
      const uint32_t qb_ = sb + OQ + (uint32_t)(warpM*32*QB) + a_off;
      const uint32_t kb_ = sb + ((kb&1) ? OK1 : OK0) + (uint32_t)(warpN*64*QB) + b_off;
#pragma unroll
      for (int k16i=0;k16i<4;k16i++){
        uint32_t af[2][4];
        ldsm4(af[0], qb_ + k16i*32);
        ldsm4(af[1], qb_ + 16*QB + k16i*32);
#pragma unroll
        for (int nf=0;nf<4;nf++){
          uint32_t bf[4];
          ldsm4(bf, kb_ + (uint32_t)(nf*16*QB) + k16i*32);
          mma16816(sacc[0][2*nf],   af[0], bf);
          mma16816(sacc[0][2*nf+1], af[0], bf+2);
          mma16816(sacc[1][2*nf],   af[1], bf);
          mma16816(sacc[1][2*nf+1], af[1], bf+2);
        }
      }
    }

    // ---- scale*adj, exp, row sums, store P fp16 ----
#pragma unroll
    for (int mi=0;mi<2;mi++){
      const int rr = r0 + mi*16;
      float rs0 = 0.f, rs8 = 0.f;
#pragma unroll
      for (int nf=0;nf<8;nf++){
        const int cc = cb + nf*8;
        float m0=1.f,m1=1.f,m2=1.f,m3=1.f;
        if (ua){
          const float* ar = adj + ((size_t)(rowg0+q0+rr))*512 + kb*128 + cc;
          float2 a01 = *reinterpret_cast<const float2*>(ar);
          float2 a23 = *reinterpret_cast<const float2*>(ar + 8*512);
          m0=a01.x; m1=a01.y; m2=a23.x; m3=a23.y;
        }
        float p0 = fexp(sacc[mi][nf][0]*0.125f*m0);
        float p1 = fexp(sacc[mi][nf][1]*0.125f*m1);
        float p2 = fexp(sacc[mi][nf][2]*0.125f*m2);
        float p3 = fexp(sacc[mi][nf][3]*0.125f*m3);
        rs0 += p0+p1;  rs8 += p2+p3;
        __half2 t0 = __halves2half2(__float2half(p0), __float2half(p1));
        __half2 t1 = __halves2half2(__float2half(p2), __float2half(p3));
        uint32_t ph01 = *reinterpret_cast<uint32_t*>(&t0);
        uint32_t ph23 = *reinterpret_cast<uint32_t*>(&t1);
        uint32_t pa = sb + OP + (uint32_t)(rr*PB + cc*2);
        asm volatile("st.shared.b32 [%0], %1;" :: "r"(pa), "r"(ph01));
        asm volatile("st.shared.b32 [%0], %1;" :: "r"(pa + 8*PB), "r"(ph23));
      }
      rs0 += __shfl_xor_sync(0xffffffffu, rs0, 1);
      rs0 += __shfl_xor_sync(0xffffffffu, rs0, 2);
      rs8 += __shfl_xor_sync(0xffffffffu, rs8, 1);
      rs8 += __shfl_xor_sync(0xffffffffu, rs8, 2);
      if ((lane&3)==0){
        lp[warpN*128 + rr]     += rs0;
        lp[warpN*128 + rr + 8] += rs8;
      }
    }
    __syncthreads();   // P visible; K[kb&1] free

    if (kb < 3){       // prefetch next K into other buffer while PV runs
      at_load_tile(sb + ((kb&1) ? OK0 : OK1), k16, krow0+128, col0, tid);
      asm volatile("cp.async.commit_group;" ::: "memory");
    }

    // ---- O += P V, V^T via ldmatrix.trans ----
    {
      const uint32_t pb2 = sb + OP + (uint32_t)(warpM*32*PB) + ap_off;
      const uint32_t vb2 = sb + OV + (uint32_t)((lane&15)*QB + (warpN*32 + (lane>>4)*8)*2);
#pragma unroll
      for (int k16i=0;k16i<8;k16i++){
        uint32_t af[2][4];
        ldsm4(af[0], pb2 + k16i*32);
        ldsm4(af[1], pb2 + 16*PB + k16i*32);
#pragma unroll
        for (int nf=0;nf<2;nf++){
          uint32_t bf[4];
          ldsm4t(bf, vb2 + (uint32_t)(k16i*16*QB) + (uint32_t)(nf*16*2));
          mma16816(oacc[0][2*nf],   af[0], bf);
          mma16816(oacc[0][2*nf+1], af[0], bf+2);
          mma16816(oacc[1][2*nf],   af[1], bf);
          mma16816(oacc[1][2*nf+1], af[1], bf+2);
        }
      }
    }
    __syncthreads();   // V reads complete

    if (kb < 3){
      at_load_tile(sb+OV, v16, krow0+128, col0, tid);
      asm volatile("cp.async.commit_group;" ::: "memory");
      asm volatile("cp.async.wait_group 0;" ::: "memory");
      __syncthreads();
    }
  }

  // ---- epilogue: normalize, store fp16 ctx ----
  if (tid < 128) lp[tid] = 1.f / (lp[tid] + lp[128 + tid]);
  __syncthreads();
#pragma unroll
  for (int mi=0;mi<2;mi++){
    const int rr = r0 + mi*16;
    const float inv0 = lp[rr], inv8 = lp[rr+8];
    const size_t rga = (size_t)(rowg0 + q0 + rr);
#pragma unroll
    for (int nf=0;nf<4;nf++){
      const int colg = col0 + warpN*32 + nf*8 + 2*(lane&3);
      *reinterpret_cast<__half2*>(&c16[rga*512 + colg]) =
          __halves2half2(__float2half(oacc[mi][nf][0]*inv0),
                         __float2half(oacc[mi][nf][1]*inv0));
      *reinterpret_cast<__half2*>(&c16[(rga+8)*512 + colg]) =
          __halves2half2(__float2half(oacc[mi][nf][2]*inv8),
                         __float2half(oacc[mi][nf][3]*inv8));
    }
  }
}

// ---------------- Gate + blend: out = c*x + (1-c)*h2 (h2 fp16) -------------
__global__ void gate_kernel(const float* __restrict__ x, const __half* __restrict__ h2,
    const float* __restrict__ gw, const float* __restrict__ gb, float* __restrict__ out)
{
  const int w = threadIdx.x>>5, lane = threadIdx.x&31;
  const int row = blockIdx.x*8 + w;
  const float* xr = x  + (size_t)row*512;
  const __half* hr = h2 + (size_t)row*512;
  float hf[16];
  float s = 0.f;
#pragma unroll
  for (int i=0;i<16;i++){
    int c = i*32 + lane;
    hf[i] = __half2float(hr[c]);
    s += xr[c]*gw[c] + hf[i]*gw[512+c];
  }
#pragma unroll
  for (int off=16;off;off>>=1) s += __shfl_xor_sync(0xffffffffu,s,off);
  s += gb[0];
  float coeff = 1.f/(1.f+__expf(-s));
  float* orow = out + (size_t)row*512;
#pragma unroll
  for (int i=0;i<16;i++){
    int c = i*32+lane;
    orow[c] = coeff*xr[c] + (1.f-coeff)*hf[i];
  }
}

// ---------------- launch ---------------------------------------------------
extern "C" void kernel_launch(void* const* d_in, const int* in_sizes, int n_in,
                              void* d_out, int out_size)
{
  const float* x   = (const float*)d_in[0];
  const float* adj = (const float*)d_in[1];
  const float* W_w = (const float*)d_in[2];
  const float* W_b = (const float*)d_in[3];
  const float* lng = (const float*)d_in[4];
  const float* lnb = (const float*)d_in[5];
  const float* Wq  = (const float*)d_in[6];
  const float* bq  = (const float*)d_in[7];
  const float* Wk  = (const float*)d_in[8];
  const float* bk  = (const float*)d_in[9];
  const float* Wv  = (const float*)d_in[10];
  const float* bv  = (const float*)d_in[11];
  const float* Wo  = (const float*)d_in[12];
  const float* bo  = (const float*)d_in[13];
  const float* gw  = (const float*)d_in[14];
  const float* gbb = (const float*)d_in[15];
  const int*   ua  = (const int*)d_in[16];
  float* out = (float*)d_out;

  __half *x16,*hp16,*h16,*q16,*k16,*v16,*c16,*h2_16,*ww,*wq,*wk,*wv,*wo;
  cudaGetSymbolAddress((void**)&x16,  g_x16);
  cudaGetSymbolAddress((void**)&hp16, g_hp16);
  cudaGetSymbolAddress((void**)&h16,  g_h16);
  cudaGetSymbolAddress((void**)&q16,  g_q16);
  cudaGetSymbolAddress((void**)&k16,  g_k16);
  cudaGetSymbolAddress((void**)&v16,  g_v16);
  cudaGetSymbolAddress((void**)&c16,  g_c16);
  cudaGetSymbolAddress((void**)&h2_16,g_h2_16);
  cudaGetSymbolAddress((void**)&ww,   g_ww);
  cudaGetSymbolAddress((void**)&wq,   g_wq);
  cudaGetSymbolAddress((void**)&wk,   g_wk);
  cudaGetSymbolAddress((void**)&wv,   g_wv);
  cudaGetSymbolAddress((void**)&wo,   g_wo);

  cudaFuncSetAttribute(gemm_mma, cudaFuncAttributeMaxDynamicSharedMemorySize, GEMM_SMEM);
  cudaFuncSetAttribute(gemm_qkv, cudaFuncAttributeMaxDynamicSharedMemorySize, GEMM_SMEM);
  cudaFuncSetAttribute(attn_mma, cudaFuncAttributeMaxDynamicSharedMemorySize, AT_SMEM);

  QKVArgs qa;
  qa.w0=wq; qa.w1=wk; qa.w2=wv;
  qa.bias0=bq; qa.bias1=bk; qa.bias2=bv;
  qa.c0=q16; qa.c1=k16; qa.c2=v16;

  TsArgs ts;
  ts.w[0]=W_w; ts.w[1]=Wq; ts.w[2]=Wk; ts.w[3]=Wv; ts.w[4]=Wo;
  ts.t[0]=ww; ts.t[1]=wq; ts.t[2]=wk; ts.t[3]=wv; ts.t[4]=wo;

  tsplit5<<<dim3(16,16,5),dim3(32,8)>>>(ts);
  conv16<<<4096,256>>>(x, x16);
  gemm_mma<<<dim3(4,32),256,GEMM_SMEM>>>(x16, ww, W_b, hp16, 0);
  ln_f16<<<8192,256>>>(hp16, lng, lnb, h16);
  gemm_qkv<<<dim3(12,32),256,GEMM_SMEM>>>(h16, qa);
  attn_mma<<<dim3(4,8,16),256,AT_SMEM>>>(q16,k16,v16,adj,ua,c16);
  gemm_mma<<<dim3(4,32),256,GEMM_SMEM>>>(c16, wo, bo, h2_16, 1);
  gate_kernel<<<1024,256>>>(x, h2_16, gw, gbb, out);
}